// round 2
// baseline (speedup 1.0000x reference)
#include <cuda_runtime.h>
#include <math.h>

#define NPTS   16384
#define NGRID  4096
#define NNODES 20480
#define GPTS   512
#define HDIM   128
#define DEG    16
#define TFIN   5

typedef unsigned long long u64;

// ---------------- scratch (device globals, no allocation) ----------------
__device__ float g_xq[NPTS * 3];
__device__ float g_hq[NPTS * HDIM];
__device__ float g_hg[NGRID * HDIM];
__device__ float g_P[NGRID * HDIM];
__device__ float g_Q[NPTS * HDIM];
__device__ float g_summ[NPTS * HDIM];

__device__ __forceinline__ float silu_f(float x) {
    return x / (1.0f + __expf(-x));
}

// ---- packed f32x2 helpers (Blackwell FFMA2 path; ptxas never auto-fuses) ----
__device__ __forceinline__ u64 pack2(float lo, float hi) {
    u64 r; asm("mov.b64 %0, {%1, %2};" : "=l"(r) : "f"(lo), "f"(hi)); return r;
}
__device__ __forceinline__ void ffma2(u64 &d, u64 a, u64 b) {
    asm("fma.rn.f32x2 %0, %1, %2, %0;" : "+l"(d) : "l"(a), "l"(b));
}
__device__ __forceinline__ float2 unpack2(u64 v) {
    float2 r; asm("mov.b64 {%0, %1}, %2;" : "=f"(r.x), "=f"(r.y) : "l"(v)); return r;
}

// 16 MACs in 8 FFMA2: p points to 16 consecutive fp32 (16B-aligned), w2 = {w,w}
#define FMA16_2(acc2, p, w2) do {                                          \
    const ulonglong2* _t = (const ulonglong2*)(p);                         \
    ulonglong2 _a = _t[0], _b = _t[1], _c = _t[2], _d = _t[3];             \
    ffma2(acc2[0], _a.x, w2); ffma2(acc2[1], _a.y, w2);                    \
    ffma2(acc2[2], _b.x, w2); ffma2(acc2[3], _b.y, w2);                    \
    ffma2(acc2[4], _c.x, w2); ffma2(acc2[5], _c.y, w2);                    \
    ffma2(acc2[6], _d.x, w2); ffma2(acc2[7], _d.y, w2);                    \
} while (0)

// ---------------- init: h_query=0, h_grid=codes, x_query=query ----------------
__global__ void init_kernel(const float* __restrict__ qp, const float* __restrict__ codes) {
    int i = blockIdx.x * blockDim.x + threadIdx.x;
    if (i < NPTS * HDIM)  g_hq[i] = 0.0f;
    if (i < NGRID * HDIM) g_hg[i] = codes[i];
    if (i < NPTS * 3)     g_xq[i] = qp[i];
}

// ---------------- projections: P = h_grid @ We1[0:128], Q = h_query @ We1[128:256] --
#define PK 20
__global__ __launch_bounds__(128) void proj_kernel(const float* __restrict__ eW1, int layer) {
    __shared__ float sA[HDIM * PK];
    const int j = threadIdx.x;
    const int base = blockIdx.x * 16;
    const bool isq = (base < NPTS);
    const float* W = eW1 + (size_t)layer * 257 * HDIM + (isq ? 128 * HDIM : 0);

    #pragma unroll
    for (int n = 0; n < 16; ++n) {
        int r = base + n;
        float v = (r < NPTS) ? g_hq[r * HDIM + j] : g_hg[(r - NPTS) * HDIM + j];
        sA[j * PK + n] = v;
    }
    __syncthreads();

    u64 acc2[8];
    #pragma unroll
    for (int p = 0; p < 8; ++p) acc2[p] = 0ull;

    #pragma unroll 4
    for (int k = 0; k < HDIM; ++k) {
        float w = __ldg(&W[k * HDIM + j]);
        u64 w2 = pack2(w, w);
        FMA16_2(acc2, sA + k * PK, w2);
    }

    float* outp = isq ? g_Q : g_P;
    int obase = isq ? base : (base - NPTS);
    #pragma unroll
    for (int p = 0; p < 8; ++p) {
        float2 v = unpack2(acc2[p]);
        outp[(obase + 2 * p + 0) * HDIM + j] = v.x;
        outp[(obase + 2 * p + 1) * HDIM + j] = v.y;
    }
}

// ---------------- edge kernel: 4 query points (64 edges) per block ----------------
#define SE   20
#define SMS  132
template <int TOUT>
__global__ __launch_bounds__(128) void edge_kernel(
    const int*   __restrict__ erow,
    const float* __restrict__ gpts,
    const float* __restrict__ eW1, const float* __restrict__ eb1,
    const float* __restrict__ eW2, const float* __restrict__ eb2,
    const float* __restrict__ coefW, const float* __restrict__ coefB,
    const float* __restrict__ qpts, float* __restrict__ out, int layer)
{
    __shared__ float sT[HDIM * SE];
    __shared__ float sM[DEG * SMS];
    __shared__ float sFc[HDIM * TOUT];
    __shared__ int   sGidx[DEG];
    __shared__ float sDist[DEG], sCm[DEG], sDx[DEG], sDy[DEG], sDz[DEG];

    const int j = threadIdx.x;
    const float wd = __ldg(&eW1[(size_t)layer * 257 * HDIM + 256 * HDIM + j]);
    const float b1 = __ldg(&eb1[layer * HDIM + j]);
    const float b2 = __ldg(&eb2[layer * HDIM + j]);
    const float* W2 = eW2 + (size_t)layer * HDIM * HDIM;

    #pragma unroll
    for (int t = 0; t < TOUT; ++t) sFc[j * TOUT + t] = coefW[j * TOUT + t];

    for (int lq = 0; lq < 4; ++lq) {
        const int q = blockIdx.x * 4 + lq;

        if (j < DEG) {
            int e = j;
            int rv = erow[q * DEG + e];
            int gidx = rv - NPTS;
            int gl = gidx & (GPTS - 1);
            float rx = gpts[gl * 3 + 0] - g_xq[q * 3 + 0];
            float ry = gpts[gl * 3 + 1] - g_xq[q * 3 + 1];
            float rz = gpts[gl * 3 + 2] - g_xq[q * 3 + 2];
            float d = sqrtf(rx * rx + ry * ry + rz * rz);
            float inv = 1.0f / (d + 1e-8f);
            sGidx[e] = gidx; sDist[e] = d;
            sDx[e] = rx * inv; sDy[e] = ry * inv; sDz[e] = rz * inv;
            float cm = 0.5f * (__cosf(d * (float)(M_PI / 10.0)) + 1.0f);
            sCm[e] = (d <= 10.0f) ? cm : 0.0f;
        }
        __syncthreads();

        // stage 1: t[k=j][e] = silu(Q[q][j] + P[gidx_e][j] + dist_e * wd_j + b1_j)
        float Qv = g_Q[q * HDIM + j] + b1;
        #pragma unroll
        for (int e = 0; e < DEG; ++e) {
            float pre = Qv + g_P[sGidx[e] * HDIM + j] + sDist[e] * wd;
            sT[j * SE + e] = silu_f(pre);
        }
        __syncthreads();

        // stage 2: m[e][j] = silu( sum_k t[e][k] * We2[k][j] + b2 ) * Cm[e]
        u64 acc2[8];
        #pragma unroll
        for (int p = 0; p < 8; ++p) acc2[p] = 0ull;
        #pragma unroll 4
        for (int k = 0; k < HDIM; ++k) {
            float w = __ldg(&W2[k * HDIM + j]);
            u64 w2 = pack2(w, w);
            FMA16_2(acc2, sT + k * SE, w2);
        }

        float msum = 0.0f;
        #pragma unroll
        for (int p = 0; p < 8; ++p) {
            float2 v = unpack2(acc2[p]);
            float m0 = silu_f(v.x + b2) * sCm[2 * p + 0];
            float m1 = silu_f(v.y + b2) * sCm[2 * p + 1];
            sM[(2 * p + 0) * SMS + j] = m0;
            sM[(2 * p + 1) * SMS + j] = m1;
            msum += m0 + m1;
        }
        if (TOUT == 1) g_summ[q * HDIM + j] = msum * (1.0f / DEG);
        __syncthreads();

        // stage 3: coef per edge, then reduce cmsg over the 16 edges
        if (j < DEG) {
            const int e = j;
            float coef[TOUT];
            #pragma unroll
            for (int t = 0; t < TOUT; ++t) coef[t] = coefB[t];
            const float4* mr = (const float4*)(sM + e * SMS);
            #pragma unroll
            for (int k4 = 0; k4 < HDIM / 4; ++k4) {
                float4 mv = mr[k4];
                #pragma unroll
                for (int t = 0; t < TOUT; ++t) {
                    coef[t] = fmaf(mv.x, sFc[(k4 * 4 + 0) * TOUT + t],
                              fmaf(mv.y, sFc[(k4 * 4 + 1) * TOUT + t],
                              fmaf(mv.z, sFc[(k4 * 4 + 2) * TOUT + t],
                              fmaf(mv.w, sFc[(k4 * 4 + 3) * TOUT + t], coef[t]))));
                }
            }
            float dir[3] = { sDx[e], sDy[e], sDz[e] };
            #pragma unroll
            for (int t = 0; t < TOUT; ++t) {
                #pragma unroll
                for (int d = 0; d < 3; ++d) {
                    float v = coef[t] * dir[d];
                    v += __shfl_down_sync(0x0000FFFFu, v, 8);
                    v += __shfl_down_sync(0x0000FFFFu, v, 4);
                    v += __shfl_down_sync(0x0000FFFFu, v, 2);
                    v += __shfl_down_sync(0x0000FFFFu, v, 1);
                    if (e == 0) {
                        if (TOUT == 1) {
                            g_xq[q * 3 + d] += v * (1.0f / DEG);
                        } else {
                            out[(q * TFIN + t) * 3 + d] =
                                (g_xq[q * 3 + d] - qpts[q * 3 + d]) + v * (1.0f / DEG);
                        }
                    }
                }
            }
        }
        __syncthreads();
    }
}

// ---------------- node kernel: h += silu([h, m_aggr] @ Wn1 + b1) @ Wn2 + b2 --------
#define SP 20
__global__ __launch_bounds__(128) void node_kernel(
    const float* __restrict__ nW1, const float* __restrict__ nb1,
    const float* __restrict__ nW2, const float* __restrict__ nb2, int layer)
{
    __shared__ float sIn[256 * SP];
    __shared__ float sU[HDIM * SP];
    const int j = threadIdx.x;
    const int base = blockIdx.x * 16;
    const float* W1 = nW1 + (size_t)layer * 256 * HDIM;
    const float* W2 = nW2 + (size_t)layer * HDIM * HDIM;
    const float bb1 = __ldg(&nb1[layer * HDIM + j]);
    const float bb2 = __ldg(&nb2[layer * HDIM + j]);

    #pragma unroll
    for (int n = 0; n < 16; ++n) {
        int node = base + n;
        float hv, mv;
        if (node < NPTS) { hv = g_hq[node * HDIM + j]; mv = g_summ[node * HDIM + j]; }
        else             { hv = g_hg[(node - NPTS) * HDIM + j]; mv = 0.0f; }
        sIn[j * SP + n] = hv;
        sIn[(128 + j) * SP + n] = mv;
    }
    __syncthreads();

    u64 acc2[8];
    #pragma unroll
    for (int p = 0; p < 8; ++p) acc2[p] = 0ull;
    #pragma unroll 4
    for (int k = 0; k < 256; ++k) {
        float w = __ldg(&W1[k * HDIM + j]);
        u64 w2 = pack2(w, w);
        FMA16_2(acc2, sIn + k * SP, w2);
    }
    #pragma unroll
    for (int p = 0; p < 8; ++p) {
        float2 v = unpack2(acc2[p]);
        sU[j * SP + 2 * p + 0] = silu_f(v.x + bb1);
        sU[j * SP + 2 * p + 1] = silu_f(v.y + bb1);
    }
    __syncthreads();

    #pragma unroll
    for (int p = 0; p < 8; ++p) acc2[p] = 0ull;
    #pragma unroll 4
    for (int k = 0; k < HDIM; ++k) {
        float w = __ldg(&W2[k * HDIM + j]);
        u64 w2 = pack2(w, w);
        FMA16_2(acc2, sU + k * SP, w2);
    }
    #pragma unroll
    for (int p = 0; p < 8; ++p) {
        float2 v = unpack2(acc2[p]);
        #pragma unroll
        for (int h = 0; h < 2; ++h) {
            int n = 2 * p + h;
            int node = base + n;
            float hnew = sIn[j * SP + n] + (h ? v.y : v.x) + bb2;
            if (node < NPTS) g_hq[node * HDIM + j] = hnew;
            else             g_hg[(node - NPTS) * HDIM + j] = hnew;
        }
    }
}

// ---------------- launch ----------------
extern "C" void kernel_launch(void* const* d_in, const int* in_sizes, int n_in,
                              void* d_out, int out_size) {
    const float* qp    = (const float*)d_in[0];
    const float* codes = (const float*)d_in[1];
    const float* gpts  = (const float*)d_in[2];
    const float* eW1   = (const float*)d_in[3];
    const float* eb1   = (const float*)d_in[4];
    const float* eW2   = (const float*)d_in[5];
    const float* eb2   = (const float*)d_in[6];
    const float* cW    = (const float*)d_in[7];
    const float* cb    = (const float*)d_in[8];
    const float* fcW   = (const float*)d_in[9];
    const float* fcb   = (const float*)d_in[10];
    const float* nW1   = (const float*)d_in[11];
    const float* nb1   = (const float*)d_in[12];
    const float* nW2   = (const float*)d_in[13];
    const float* nb2   = (const float*)d_in[14];
    const int*   eidx  = (const int*)d_in[15];
    float* out = (float*)d_out;

    init_kernel<<<(NPTS * HDIM + 255) / 256, 256>>>(qp, codes);

    for (int L = 0; L < 4; ++L) {
        proj_kernel<<<NNODES / 16, 128>>>(eW1, L);
        if (L < 3) {
            edge_kernel<1><<<NPTS / 4, 128>>>(eidx, gpts, eW1, eb1, eW2, eb2,
                                              cW + L * HDIM, cb + L, qp, nullptr, L);
            node_kernel<<<NNODES / 16, 128>>>(nW1, nb1, nW2, nb2, L);
        } else {
            edge_kernel<TFIN><<<NPTS / 4, 128>>>(eidx, gpts, eW1, eb1, eW2, eb2,
                                                 fcW, fcb, qp, out, L);
        }
    }
}

// round 3
// speedup vs baseline: 1.3726x; 1.3726x over previous
#include <cuda_runtime.h>
#include <math.h>

#define NPTS   16384
#define NGRID  4096
#define NNODES 20480
#define GPTS   512
#define HDIM   128
#define DEG    16
#define TFIN   5

// ---------------- scratch (device globals, no allocation) ----------------
__device__ float g_xq[NPTS * 3];
__device__ float g_hq[NPTS * HDIM];
__device__ float g_hg[NGRID * HDIM];
__device__ float g_P[NGRID * HDIM];
__device__ float g_Q[NPTS * HDIM];
__device__ float g_summ[NPTS * HDIM];

__device__ __forceinline__ float silu_f(float x) {
    // fast: MUFU.EX2 + MUFU.RCP; |rel err| ~1e-6, way under tolerance
    return __fdividef(x, 1.0f + __expf(-x));
}

__device__ __forceinline__ float4 ldg4(const float* p) {
    return __ldg((const float4*)p);
}

// 4x4 outer product: acc[mi] (float4 over j) += a[mi] * b[j]
#define FMA_TILE(acc, a, b) do {                                             \
    acc[0].x = fmaf(a.x, b.x, acc[0].x); acc[0].y = fmaf(a.x, b.y, acc[0].y);\
    acc[0].z = fmaf(a.x, b.z, acc[0].z); acc[0].w = fmaf(a.x, b.w, acc[0].w);\
    acc[1].x = fmaf(a.y, b.x, acc[1].x); acc[1].y = fmaf(a.y, b.y, acc[1].y);\
    acc[1].z = fmaf(a.y, b.z, acc[1].z); acc[1].w = fmaf(a.y, b.w, acc[1].w);\
    acc[2].x = fmaf(a.z, b.x, acc[2].x); acc[2].y = fmaf(a.z, b.y, acc[2].y);\
    acc[2].z = fmaf(a.z, b.z, acc[2].z); acc[2].w = fmaf(a.z, b.w, acc[2].w);\
    acc[3].x = fmaf(a.w, b.x, acc[3].x); acc[3].y = fmaf(a.w, b.y, acc[3].y);\
    acc[3].z = fmaf(a.w, b.z, acc[3].z); acc[3].w = fmaf(a.w, b.w, acc[3].w);\
} while (0)

#define ZERO4(acc) do {                                                      \
    acc[0] = make_float4(0.f,0.f,0.f,0.f); acc[1] = make_float4(0.f,0.f,0.f,0.f); \
    acc[2] = make_float4(0.f,0.f,0.f,0.f); acc[3] = make_float4(0.f,0.f,0.f,0.f); \
} while (0)

// ---------------- init: h_query=0, h_grid=codes, x_query=query ----------------
__global__ void init_kernel(const float* __restrict__ qp, const float* __restrict__ codes) {
    int i = blockIdx.x * blockDim.x + threadIdx.x;
    if (i < NPTS * HDIM)  g_hq[i] = 0.0f;
    if (i < NGRID * HDIM) g_hg[i] = codes[i];
    if (i < NPTS * 3)     g_xq[i] = qp[i];
}

// ---------------- projections: P = h_grid @ We1[0:128], Q = h_query @ We1[128:256] --
#define PK 20
__global__ __launch_bounds__(128) void proj_kernel(const float* __restrict__ eW1, int layer) {
    __shared__ float sA[HDIM * PK];          // [k][m], m = 16 rows
    const int tid = threadIdx.x;
    const int j4 = (tid & 31) * 4;
    const int mq = tid >> 5;
    const int base = blockIdx.x * 16;
    const bool isq = (base < NPTS);
    const float* W = eW1 + (size_t)layer * 257 * HDIM + (isq ? 128 * HDIM : 0);

    #pragma unroll
    for (int n = 0; n < 16; ++n) {
        int r = base + n;
        float v = (r < NPTS) ? g_hq[r * HDIM + tid] : g_hg[(r - NPTS) * HDIM + tid];
        sA[tid * PK + n] = v;
    }
    __syncthreads();

    float4 acc[4]; ZERO4(acc);
    #pragma unroll 4
    for (int k = 0; k < HDIM; ++k) {
        float4 a = *(const float4*)(sA + k * PK + mq * 4);
        float4 b = ldg4(W + k * HDIM + j4);
        FMA_TILE(acc, a, b);
    }

    float* outp = isq ? g_Q : g_P;
    int obase = isq ? base : (base - NPTS);
    #pragma unroll
    for (int mi = 0; mi < 4; ++mi) {
        int row = obase + mq * 4 + mi;
        *(float4*)(outp + row * HDIM + j4) = acc[mi];
    }
}

// ---------------- edge kernel: 4 query points per block, 4x4 register tiling ------
#define ST   20
#define SMS  132
template <int TOUT>
__global__ __launch_bounds__(128) void edge_kernel(
    const int*   __restrict__ erow,
    const float* __restrict__ gpts,
    const float* __restrict__ eW1, const float* __restrict__ eb1,
    const float* __restrict__ eW2, const float* __restrict__ eb2,
    const float* __restrict__ coefW, const float* __restrict__ coefB,
    const float* __restrict__ qpts, float* __restrict__ out, int layer)
{
    __shared__ float sT[HDIM * ST];          // [k][e]
    __shared__ float sM[DEG * SMS];          // [e][j]
    __shared__ float sFc[HDIM * TOUT];
    __shared__ int   sGidx[DEG];
    __shared__ float sDist[DEG], sCm[DEG], sDx[DEG], sDy[DEG], sDz[DEG];

    const int tid = threadIdx.x;
    const int j4 = (tid & 31) * 4;
    const int mq = tid >> 5;
    const float  wd  = __ldg(&eW1[(size_t)layer * 257 * HDIM + 256 * HDIM + tid]);
    const float  b1  = __ldg(&eb1[layer * HDIM + tid]);
    const float4 bi2 = ldg4(eb2 + layer * HDIM + j4);
    const float* W2  = eW2 + (size_t)layer * HDIM * HDIM;

    #pragma unroll
    for (int t = 0; t < TOUT; ++t) sFc[tid * TOUT + t] = coefW[tid * TOUT + t];

    for (int lq = 0; lq < 4; ++lq) {
        const int q = blockIdx.x * 4 + lq;

        if (tid < DEG) {
            int e = tid;
            int rv = erow[q * DEG + e];
            int gidx = rv - NPTS;
            int gl = gidx & (GPTS - 1);
            float rx = gpts[gl * 3 + 0] - g_xq[q * 3 + 0];
            float ry = gpts[gl * 3 + 1] - g_xq[q * 3 + 1];
            float rz = gpts[gl * 3 + 2] - g_xq[q * 3 + 2];
            float d = sqrtf(rx * rx + ry * ry + rz * rz);
            float inv = 1.0f / (d + 1e-8f);
            sGidx[e] = gidx; sDist[e] = d;
            sDx[e] = rx * inv; sDy[e] = ry * inv; sDz[e] = rz * inv;
            float cm = 0.5f * (__cosf(d * (float)(M_PI / 10.0)) + 1.0f);
            sCm[e] = (d <= 10.0f) ? cm : 0.0f;
        }
        __syncthreads();

        // stage 1: sT[k=tid][e] = silu(Q[q][k] + P[g_e][k] + d_e*wd_k + b1_k)
        float Qv = g_Q[q * HDIM + tid] + b1;
        #pragma unroll
        for (int e = 0; e < DEG; ++e) {
            float pre = Qv + g_P[sGidx[e] * HDIM + tid] + sDist[e] * wd;
            sT[tid * ST + e] = silu_f(pre);
        }
        __syncthreads();

        // stage 2: M[16x128] = silu(T[16x128] @ W2 + b2) * Cm  — 4x4 register tile
        float4 acc[4]; ZERO4(acc);
        #pragma unroll 4
        for (int k = 0; k < HDIM; ++k) {
            float4 a = *(const float4*)(sT + k * ST + mq * 4);   // 4 edges (broadcast)
            float4 b = ldg4(W2 + k * HDIM + j4);                 // 4 cols (coalesced, L1)
            FMA_TILE(acc, a, b);
        }
        #pragma unroll
        for (int mi = 0; mi < 4; ++mi) {
            int e = mq * 4 + mi;
            float cm = sCm[e];
            float4 mv;
            mv.x = silu_f(acc[mi].x + bi2.x) * cm;
            mv.y = silu_f(acc[mi].y + bi2.y) * cm;
            mv.z = silu_f(acc[mi].z + bi2.z) * cm;
            mv.w = silu_f(acc[mi].w + bi2.w) * cm;
            *(float4*)(sM + e * SMS + j4) = mv;
        }
        __syncthreads();

        // m_aggr for node update (layers 0..2)
        if (TOUT == 1) {
            float s = 0.0f;
            #pragma unroll
            for (int e = 0; e < DEG; ++e) s += sM[e * SMS + tid];
            g_summ[q * HDIM + tid] = s * (1.0f / DEG);
        }

        // stage 3: coef per edge, reduce cmsg over the 16 edges
        if (tid < DEG) {
            const int e = tid;
            float coef[TOUT];
            #pragma unroll
            for (int t = 0; t < TOUT; ++t) coef[t] = coefB[t];
            const float4* mr = (const float4*)(sM + e * SMS);
            #pragma unroll
            for (int k4 = 0; k4 < HDIM / 4; ++k4) {
                float4 mv = mr[k4];
                #pragma unroll
                for (int t = 0; t < TOUT; ++t) {
                    coef[t] = fmaf(mv.x, sFc[(k4 * 4 + 0) * TOUT + t],
                              fmaf(mv.y, sFc[(k4 * 4 + 1) * TOUT + t],
                              fmaf(mv.z, sFc[(k4 * 4 + 2) * TOUT + t],
                              fmaf(mv.w, sFc[(k4 * 4 + 3) * TOUT + t], coef[t]))));
                }
            }
            float dir[3] = { sDx[e], sDy[e], sDz[e] };
            #pragma unroll
            for (int t = 0; t < TOUT; ++t) {
                #pragma unroll
                for (int d = 0; d < 3; ++d) {
                    float v = coef[t] * dir[d];
                    v += __shfl_down_sync(0x0000FFFFu, v, 8);
                    v += __shfl_down_sync(0x0000FFFFu, v, 4);
                    v += __shfl_down_sync(0x0000FFFFu, v, 2);
                    v += __shfl_down_sync(0x0000FFFFu, v, 1);
                    if (e == 0) {
                        if (TOUT == 1) {
                            g_xq[q * 3 + d] += v * (1.0f / DEG);
                        } else {
                            out[(q * TFIN + t) * 3 + d] =
                                (g_xq[q * 3 + d] - qpts[q * 3 + d]) + v * (1.0f / DEG);
                        }
                    }
                }
            }
        }
        __syncthreads();
    }
}

// ---------------- node kernel: h += silu([h, m_aggr] @ Wn1 + b1) @ Wn2 + b2 --------
#define SP 20
__global__ __launch_bounds__(128) void node_kernel(
    const float* __restrict__ nW1, const float* __restrict__ nb1,
    const float* __restrict__ nW2, const float* __restrict__ nb2, int layer)
{
    __shared__ float sIn[256 * SP];          // [k][m] input features
    __shared__ float sU[HDIM * SP];          // [k][m] hidden
    const int tid = threadIdx.x;
    const int j4 = (tid & 31) * 4;
    const int mq = tid >> 5;
    const int base = blockIdx.x * 16;
    const float* W1 = nW1 + (size_t)layer * 256 * HDIM;
    const float* W2 = nW2 + (size_t)layer * HDIM * HDIM;
    const float4 bb1 = ldg4(nb1 + layer * HDIM + j4);
    const float4 bb2 = ldg4(nb2 + layer * HDIM + j4);

    #pragma unroll
    for (int n = 0; n < 16; ++n) {
        int node = base + n;
        float hv, mv;
        if (node < NPTS) { hv = g_hq[node * HDIM + tid]; mv = g_summ[node * HDIM + tid]; }
        else             { hv = g_hg[(node - NPTS) * HDIM + tid]; mv = 0.0f; }
        sIn[tid * SP + n] = hv;
        sIn[(128 + tid) * SP + n] = mv;
    }
    __syncthreads();

    // GEMM1: U[16x128] = silu(In[16x256] @ W1 + b1)
    float4 acc[4]; ZERO4(acc);
    #pragma unroll 4
    for (int k = 0; k < 256; ++k) {
        float4 a = *(const float4*)(sIn + k * SP + mq * 4);
        float4 b = ldg4(W1 + k * HDIM + j4);
        FMA_TILE(acc, a, b);
    }
    // transpose-store into sU[k=hidden][m]
    {
        float4 c;
        c = make_float4(silu_f(acc[0].x + bb1.x), silu_f(acc[1].x + bb1.x),
                        silu_f(acc[2].x + bb1.x), silu_f(acc[3].x + bb1.x));
        *(float4*)(sU + (j4 + 0) * SP + mq * 4) = c;
        c = make_float4(silu_f(acc[0].y + bb1.y), silu_f(acc[1].y + bb1.y),
                        silu_f(acc[2].y + bb1.y), silu_f(acc[3].y + bb1.y));
        *(float4*)(sU + (j4 + 1) * SP + mq * 4) = c;
        c = make_float4(silu_f(acc[0].z + bb1.z), silu_f(acc[1].z + bb1.z),
                        silu_f(acc[2].z + bb1.z), silu_f(acc[3].z + bb1.z));
        *(float4*)(sU + (j4 + 2) * SP + mq * 4) = c;
        c = make_float4(silu_f(acc[0].w + bb1.w), silu_f(acc[1].w + bb1.w),
                        silu_f(acc[2].w + bb1.w), silu_f(acc[3].w + bb1.w));
        *(float4*)(sU + (j4 + 3) * SP + mq * 4) = c;
    }
    __syncthreads();

    // GEMM2: dh[16x128] = U @ W2 + b2;  h += dh
    ZERO4(acc);
    #pragma unroll 4
    for (int k = 0; k < HDIM; ++k) {
        float4 a = *(const float4*)(sU + k * SP + mq * 4);
        float4 b = ldg4(W2 + k * HDIM + j4);
        FMA_TILE(acc, a, b);
    }
    #pragma unroll
    for (int mi = 0; mi < 4; ++mi) {
        int node = base + mq * 4 + mi;
        float* hp = (node < NPTS) ? (g_hq + node * HDIM) : (g_hg + (node - NPTS) * HDIM);
        float4 hold = *(const float4*)(hp + j4);
        float4 o;
        o.x = hold.x + acc[mi].x + bb2.x;
        o.y = hold.y + acc[mi].y + bb2.y;
        o.z = hold.z + acc[mi].z + bb2.z;
        o.w = hold.w + acc[mi].w + bb2.w;
        *(float4*)(hp + j4) = o;
    }
}

// ---------------- launch ----------------
extern "C" void kernel_launch(void* const* d_in, const int* in_sizes, int n_in,
                              void* d_out, int out_size) {
    const float* qp    = (const float*)d_in[0];
    const float* codes = (const float*)d_in[1];
    const float* gpts  = (const float*)d_in[2];
    const float* eW1   = (const float*)d_in[3];
    const float* eb1   = (const float*)d_in[4];
    const float* eW2   = (const float*)d_in[5];
    const float* eb2   = (const float*)d_in[6];
    const float* cW    = (const float*)d_in[7];
    const float* cb    = (const float*)d_in[8];
    const float* fcW   = (const float*)d_in[9];
    const float* fcb   = (const float*)d_in[10];
    const float* nW1   = (const float*)d_in[11];
    const float* nb1   = (const float*)d_in[12];
    const float* nW2   = (const float*)d_in[13];
    const float* nb2   = (const float*)d_in[14];
    const int*   eidx  = (const int*)d_in[15];
    float* out = (float*)d_out;

    init_kernel<<<(NPTS * HDIM + 255) / 256, 256>>>(qp, codes);

    for (int L = 0; L < 4; ++L) {
        proj_kernel<<<NNODES / 16, 128>>>(eW1, L);
        if (L < 3) {
            edge_kernel<1><<<NPTS / 4, 128>>>(eidx, gpts, eW1, eb1, eW2, eb2,
                                              cW + L * HDIM, cb + L, qp, nullptr, L);
            node_kernel<<<NNODES / 16, 128>>>(nW1, nb1, nW2, nb2, L);
        } else {
            edge_kernel<TFIN><<<NPTS / 4, 128>>>(eidx, gpts, eW1, eb1, eW2, eb2,
                                                 fcW, fcb, qp, out, L);
        }
    }
}

// round 6
// speedup vs baseline: 1.9819x; 1.4439x over previous
#include <cuda_runtime.h>
#include <math.h>
#include <stdint.h>

#define NPTS   16384
#define NGRID  4096
#define NNODES 20480
#define GPTS   512
#define HDIM   128
#define DEG    16
#define TFIN   5

// ---------------- scratch (device globals, no allocation) ----------------
__device__ float g_xq[NPTS * 3];
__device__ float g_hq[NPTS * HDIM];
__device__ float g_hg[NGRID * HDIM];
__device__ float g_P[NGRID * HDIM];
__device__ float g_Q[NPTS * HDIM];
__device__ float g_summ[NPTS * HDIM];
__device__ float g_W2T[4 * HDIM * HDIM];   // W2^T per layer: [j][k], tf32-rounded

__device__ __forceinline__ float silu_f(float x) {
    return __fdividef(x, 1.0f + __expf(-x));
}
__device__ __forceinline__ float4 ldg4(const float* p) {
    return __ldg((const float4*)p);
}
__device__ __forceinline__ float tf32r(float v) {
    uint32_t t; asm("cvt.rna.tf32.f32 %0, %1;" : "=r"(t) : "f"(v));
    return __uint_as_float(t);
}
__device__ __forceinline__ void mma_tf32(float* c, uint32_t a0, uint32_t a1,
                                         uint32_t a2, uint32_t a3,
                                         uint32_t b0, uint32_t b1) {
    asm volatile(
        "mma.sync.aligned.m16n8k8.row.col.f32.tf32.tf32.f32 "
        "{%0,%1,%2,%3}, {%4,%5,%6,%7}, {%8,%9}, {%0,%1,%2,%3};"
        : "+f"(c[0]), "+f"(c[1]), "+f"(c[2]), "+f"(c[3])
        : "r"(a0), "r"(a1), "r"(a2), "r"(a3), "r"(b0), "r"(b1));
}

// ---- 4x4 scalar tile helpers (proj / node kernels) ----
#define FMA_TILE(acc, a, b) do {                                             \
    acc[0].x = fmaf(a.x, b.x, acc[0].x); acc[0].y = fmaf(a.x, b.y, acc[0].y);\
    acc[0].z = fmaf(a.x, b.z, acc[0].z); acc[0].w = fmaf(a.x, b.w, acc[0].w);\
    acc[1].x = fmaf(a.y, b.x, acc[1].x); acc[1].y = fmaf(a.y, b.y, acc[1].y);\
    acc[1].z = fmaf(a.y, b.z, acc[1].z); acc[1].w = fmaf(a.y, b.w, acc[1].w);\
    acc[2].x = fmaf(a.z, b.x, acc[2].x); acc[2].y = fmaf(a.z, b.y, acc[2].y);\
    acc[2].z = fmaf(a.z, b.z, acc[2].z); acc[2].w = fmaf(a.z, b.w, acc[2].w);\
    acc[3].x = fmaf(a.w, b.x, acc[3].x); acc[3].y = fmaf(a.w, b.y, acc[3].y);\
    acc[3].z = fmaf(a.w, b.z, acc[3].z); acc[3].w = fmaf(a.w, b.w, acc[3].w);\
} while (0)
#define ZERO4(acc) do {                                                      \
    acc[0] = make_float4(0.f,0.f,0.f,0.f); acc[1] = make_float4(0.f,0.f,0.f,0.f); \
    acc[2] = make_float4(0.f,0.f,0.f,0.f); acc[3] = make_float4(0.f,0.f,0.f,0.f); \
} while (0)

// ---------------- init ----------------
__global__ void init_kernel(const float* __restrict__ qp, const float* __restrict__ codes) {
    int i = blockIdx.x * blockDim.x + threadIdx.x;
    if (i < NPTS * HDIM)  g_hq[i] = 0.0f;
    if (i < NGRID * HDIM) g_hg[i] = codes[i];
    if (i < NPTS * 3)     g_xq[i] = qp[i];
}

// ---------------- W2^T transpose + tf32 round (4 layers, once per launch) --------
__global__ void w2t_kernel(const float* __restrict__ eW2) {
    int i = blockIdx.x * blockDim.x + threadIdx.x;
    if (i >= 4 * HDIM * HDIM) return;
    int layer = i >> 14;
    int rem = i & 16383;
    int j = rem >> 7;          // output row (N index)
    int k = rem & 127;         // output col (K index)
    g_W2T[i] = tf32r(eW2[layer * 16384 + k * HDIM + j]);
}

// ---------------- projections (validated R3 version) ----------------
#define PK 20
__global__ __launch_bounds__(128) void proj_kernel(const float* __restrict__ eW1, int layer) {
    __shared__ float sA[HDIM * PK];
    const int tid = threadIdx.x;
    const int j4 = (tid & 31) * 4;
    const int mq = tid >> 5;
    const int base = blockIdx.x * 16;
    const bool isq = (base < NPTS);
    const float* W = eW1 + (size_t)layer * 257 * HDIM + (isq ? 128 * HDIM : 0);

    #pragma unroll
    for (int n = 0; n < 16; ++n) {
        int r = base + n;
        float v = (r < NPTS) ? g_hq[r * HDIM + tid] : g_hg[(r - NPTS) * HDIM + tid];
        sA[tid * PK + n] = v;
    }
    __syncthreads();

    float4 acc[4]; ZERO4(acc);
    #pragma unroll 4
    for (int k = 0; k < HDIM; ++k) {
        float4 a = *(const float4*)(sA + k * PK + mq * 4);
        float4 b = ldg4(W + k * HDIM + j4);
        FMA_TILE(acc, a, b);
    }
    float* outp = isq ? g_Q : g_P;
    int obase = isq ? base : (base - NPTS);
    #pragma unroll
    for (int mi = 0; mi < 4; ++mi)
        *(float4*)(outp + (obase + mq * 4 + mi) * HDIM + j4) = acc[mi];
}

// ---------------- edge kernel: mma.sync tf32, M=64 (4 queries) per block ---------
// dynamic smem layout (bytes):
#define OFF_T     0          // A tile / M tile: 64 x 132 fp32 = 33792
#define OFF_B     33792      // W2T staged: 128 x 132 fp32 = 67584
#define OFF_GIDX  101376
#define OFF_DIST  101632
#define OFF_DX    101888
#define OFF_DY    102144
#define OFF_DZ    102400
#define OFF_CM    102656
#define OFF_B2    102912     // 512
#define OFF_FC    103424     // up to 128*5*4 = 2560
#define OFF_COEF  105984     // up to 64*5*4 = 1280
#define EDGE_SMEM 107520

template <int TOUT>
__global__ __launch_bounds__(256) void edge_mma_kernel(
    const int*   __restrict__ erow,
    const float* __restrict__ gpts,
    const float* __restrict__ eW1, const float* __restrict__ eb1,
    const float* __restrict__ eb2,
    const float* __restrict__ coefW, const float* __restrict__ coefB,
    const float* __restrict__ qpts, float* __restrict__ out, int layer)
{
    extern __shared__ char sb[];
    float* sT    = (float*)(sb + OFF_T);     // A, later reused as M
    float* sB    = (float*)(sb + OFF_B);
    int*   sGidx = (int*)  (sb + OFF_GIDX);
    float* sDist = (float*)(sb + OFF_DIST);
    float* sDx   = (float*)(sb + OFF_DX);
    float* sDy   = (float*)(sb + OFF_DY);
    float* sDz   = (float*)(sb + OFF_DZ);
    float* sCm   = (float*)(sb + OFF_CM);
    float* sB2   = (float*)(sb + OFF_B2);
    float* sFc   = (float*)(sb + OFF_FC);
    float* sCoef = (float*)(sb + OFF_COEF);

    const int tid = threadIdx.x;
    const int wid = tid >> 5;
    const int lane = tid & 31;
    const int bq4 = blockIdx.x * 4;

    // stage B: 64KB pre-transposed tf32 W2T into padded [n][132]
    {
        const float4* src = (const float4*)(g_W2T + layer * 16384);
        #pragma unroll
        for (int i = 0; i < 16; ++i) {
            int idx = tid + i * 256;          // float4 index, 0..4095
            float4 v = src[idx];
            int flat = idx * 4;
            int n = flat >> 7, k = flat & 127;
            *(float4*)(sB + n * 132 + k) = v;
        }
    }
    if (tid < 128) {
        sB2[tid] = eb2[layer * HDIM + tid];
        #pragma unroll
        for (int t = 0; t < TOUT; ++t) sFc[tid * TOUT + t] = coefW[tid * TOUT + t];
    }
    // geometry for 64 edges
    if (tid < 64) {
        int e = tid;
        int q = bq4 + (e >> 4);
        int rv = erow[q * DEG + (e & 15)];
        int gidx = rv - NPTS;
        int gl = gidx & (GPTS - 1);
        float rx = gpts[gl * 3 + 0] - g_xq[q * 3 + 0];
        float ry = gpts[gl * 3 + 1] - g_xq[q * 3 + 1];
        float rz = gpts[gl * 3 + 2] - g_xq[q * 3 + 2];
        float d = sqrtf(rx * rx + ry * ry + rz * rz);
        float inv = 1.0f / (d + 1e-8f);
        sGidx[e] = gidx; sDist[e] = d;
        sDx[e] = rx * inv; sDy[e] = ry * inv; sDz[e] = rz * inv;
        float cm = 0.5f * (__cosf(d * (float)(M_PI / 10.0)) + 1.0f);
        sCm[e] = (d <= 10.0f) ? cm : 0.0f;
    }
    __syncthreads();

    // stage 1: A[e][k] = tf32(silu(Q[q][k] + P[gidx][k] + dist*wd[k] + b1[k]))
    const float* W1L = eW1 + (size_t)layer * 257 * HDIM;
    #pragma unroll
    for (int it = 0; it < 8; ++it) {
        int idx = tid + it * 256;
        int e = idx >> 5;
        int k4 = (idx & 31) * 4;
        int q = bq4 + (e >> 4);
        float4 Qv = ldg4(g_Q + q * HDIM + k4);
        float4 Pv = ldg4(g_P + sGidx[e] * HDIM + k4);
        float4 wd = ldg4(W1L + 256 * HDIM + k4);
        float4 b1 = ldg4(eb1 + layer * HDIM + k4);
        float dd = sDist[e];
        float4 r;
        r.x = tf32r(silu_f(Qv.x + Pv.x + dd * wd.x + b1.x));
        r.y = tf32r(silu_f(Qv.y + Pv.y + dd * wd.y + b1.y));
        r.z = tf32r(silu_f(Qv.z + Pv.z + dd * wd.z + b1.z));
        r.w = tf32r(silu_f(Qv.w + Pv.w + dd * wd.w + b1.w));
        *(float4*)(sT + e * 132 + k4) = r;
    }
    __syncthreads();

    // mma: warp grid 4(m) x 2(n); warp tile 16 rows x 64 cols
    const int mw = wid & 3;
    const int nw = wid >> 2;
    float c[8][4];
    #pragma unroll
    for (int nt = 0; nt < 8; ++nt)
        #pragma unroll
        for (int i = 0; i < 4; ++i) c[nt][i] = 0.0f;

    const int arow = mw * 16 + (lane >> 2);
    const int bn   = nw * 64 + (lane >> 2);
    const int kl   = lane & 3;
    #pragma unroll
    for (int k8 = 0; k8 < 16; ++k8) {
        int kc = k8 * 8 + kl;
        uint32_t a0 = __float_as_uint(sT[arow * 132 + kc]);
        uint32_t a1 = __float_as_uint(sT[(arow + 8) * 132 + kc]);
        uint32_t a2 = __float_as_uint(sT[arow * 132 + kc + 4]);
        uint32_t a3 = __float_as_uint(sT[(arow + 8) * 132 + kc + 4]);
        #pragma unroll
        for (int nt = 0; nt < 8; ++nt) {
            const float* bp = sB + (bn + nt * 8) * 132 + kc;
            uint32_t b0 = __float_as_uint(bp[0]);
            uint32_t b1 = __float_as_uint(bp[4]);
            mma_tf32(c[nt], a0, a1, a2, a3, b0, b1);
        }
    }
    __syncthreads();   // all warps done reading sT (A)

    // epilogue: M[e][j] = silu(D + b2[j]) * Cm[e], into sT (reused as sM)
    {
        const int r0 = mw * 16 + (lane >> 2);
        const int r1 = r0 + 8;
        const float cm0 = sCm[r0], cm1 = sCm[r1];
        #pragma unroll
        for (int nt = 0; nt < 8; ++nt) {
            int c0 = nw * 64 + nt * 8 + 2 * (lane & 3);
            float bz0 = sB2[c0], bz1 = sB2[c0 + 1];
            sT[r0 * 132 + c0]     = silu_f(c[nt][0] + bz0) * cm0;
            sT[r0 * 132 + c0 + 1] = silu_f(c[nt][1] + bz1) * cm0;
            sT[r1 * 132 + c0]     = silu_f(c[nt][2] + bz0) * cm1;
            sT[r1 * 132 + c0 + 1] = silu_f(c[nt][3] + bz1) * cm1;
        }
    }
    __syncthreads();

    // m_aggr (layers 0..2)
    if (TOUT == 1) {
        #pragma unroll
        for (int it = 0; it < 2; ++it) {
            int idx = tid + it * 256;
            int q = idx >> 7;
            int j = idx & 127;
            float s = 0.0f;
            #pragma unroll
            for (int e = 0; e < DEG; ++e) s += sT[(q * DEG + e) * 132 + j];
            g_summ[(bq4 + q) * HDIM + j] = s * (1.0f / DEG);
        }
    }

    // coef: 64 edges, 4 threads/edge
    {
        int e = tid >> 2, part = tid & 3;
        float acc[TOUT];
        #pragma unroll
        for (int t = 0; t < TOUT; ++t) acc[t] = 0.0f;
        const float* mr = sT + e * 132 + part * 32;
        #pragma unroll 8
        for (int i = 0; i < 32; ++i) {
            float mv = mr[i];
            int j = part * 32 + i;
            #pragma unroll
            for (int t = 0; t < TOUT; ++t) acc[t] = fmaf(mv, sFc[j * TOUT + t], acc[t]);
        }
        #pragma unroll
        for (int t = 0; t < TOUT; ++t) {
            float v = acc[t];
            v += __shfl_down_sync(0xFFFFFFFFu, v, 2);
            v += __shfl_down_sync(0xFFFFFFFFu, v, 1);
            if (part == 0) sCoef[e * TOUT + t] = v + __ldg(&coefB[t]);
        }
    }
    __syncthreads();

    // final reduction over 16 edges per query
    if (TOUT == 1) {
        if (tid < 12) {
            int q = tid / 3, d = tid % 3;
            const float* dirp = (d == 0) ? sDx : (d == 1) ? sDy : sDz;
            float s = 0.0f;
            #pragma unroll
            for (int e = 0; e < DEG; ++e) s += sCoef[q * DEG + e] * dirp[q * DEG + e];
            g_xq[(bq4 + q) * 3 + d] += s * (1.0f / DEG);
        }
    } else {
        if (tid < 4 * TOUT * 3) {
            int q = tid / (TOUT * 3);
            int r = tid % (TOUT * 3);
            int t = r / 3, d = r % 3;
            const float* dirp = (d == 0) ? sDx : (d == 1) ? sDy : sDz;
            float s = 0.0f;
            #pragma unroll
            for (int e = 0; e < DEG; ++e)
                s += sCoef[(q * DEG + e) * TOUT + t] * dirp[q * DEG + e];
            int gq = bq4 + q;
            out[(gq * TFIN + t) * 3 + d] =
                (g_xq[gq * 3 + d] - qpts[gq * 3 + d]) + s * (1.0f / DEG);
        }
    }
}

// ---------------- node kernel (validated R3 version) ----------------
#define SP 20
__global__ __launch_bounds__(128) void node_kernel(
    const float* __restrict__ nW1, const float* __restrict__ nb1,
    const float* __restrict__ nW2, const float* __restrict__ nb2, int layer)
{
    __shared__ float sIn[256 * SP];
    __shared__ float sU[HDIM * SP];
    const int tid = threadIdx.x;
    const int j4 = (tid & 31) * 4;
    const int mq = tid >> 5;
    const int base = blockIdx.x * 16;
    const float* W1 = nW1 + (size_t)layer * 256 * HDIM;
    const float* W2 = nW2 + (size_t)layer * HDIM * HDIM;
    const float4 bb1 = ldg4(nb1 + layer * HDIM + j4);
    const float4 bb2 = ldg4(nb2 + layer * HDIM + j4);

    #pragma unroll
    for (int n = 0; n < 16; ++n) {
        int node = base + n;
        float hv, mv;
        if (node < NPTS) { hv = g_hq[node * HDIM + tid]; mv = g_summ[node * HDIM + tid]; }
        else             { hv = g_hg[(node - NPTS) * HDIM + tid]; mv = 0.0f; }
        sIn[tid * SP + n] = hv;
        sIn[(128 + tid) * SP + n] = mv;
    }
    __syncthreads();

    float4 acc[4]; ZERO4(acc);
    #pragma unroll 4
    for (int k = 0; k < 256; ++k) {
        float4 a = *(const float4*)(sIn + k * SP + mq * 4);
        float4 b = ldg4(W1 + k * HDIM + j4);
        FMA_TILE(acc, a, b);
    }
    {
        float4 cc;
        cc = make_float4(silu_f(acc[0].x + bb1.x), silu_f(acc[1].x + bb1.x),
                         silu_f(acc[2].x + bb1.x), silu_f(acc[3].x + bb1.x));
        *(float4*)(sU + (j4 + 0) * SP + mq * 4) = cc;
        cc = make_float4(silu_f(acc[0].y + bb1.y), silu_f(acc[1].y + bb1.y),
                         silu_f(acc[2].y + bb1.y), silu_f(acc[3].y + bb1.y));
        *(float4*)(sU + (j4 + 1) * SP + mq * 4) = cc;
        cc = make_float4(silu_f(acc[0].z + bb1.z), silu_f(acc[1].z + bb1.z),
                         silu_f(acc[2].z + bb1.z), silu_f(acc[3].z + bb1.z));
        *(float4*)(sU + (j4 + 2) * SP + mq * 4) = cc;
        cc = make_float4(silu_f(acc[0].w + bb1.w), silu_f(acc[1].w + bb1.w),
                         silu_f(acc[2].w + bb1.w), silu_f(acc[3].w + bb1.w));
        *(float4*)(sU + (j4 + 3) * SP + mq * 4) = cc;
    }
    __syncthreads();

    ZERO4(acc);
    #pragma unroll 4
    for (int k = 0; k < HDIM; ++k) {
        float4 a = *(const float4*)(sU + k * SP + mq * 4);
        float4 b = ldg4(W2 + k * HDIM + j4);
        FMA_TILE(acc, a, b);
    }
    #pragma unroll
    for (int mi = 0; mi < 4; ++mi) {
        int node = base + mq * 4 + mi;
        float* hp = (node < NPTS) ? (g_hq + node * HDIM) : (g_hg + (node - NPTS) * HDIM);
        float4 hold = *(const float4*)(hp + j4);
        float4 o;
        o.x = hold.x + acc[mi].x + bb2.x;
        o.y = hold.y + acc[mi].y + bb2.y;
        o.z = hold.z + acc[mi].z + bb2.z;
        o.w = hold.w + acc[mi].w + bb2.w;
        *(float4*)(hp + j4) = o;
    }
}

// ---------------- launch ----------------
extern "C" void kernel_launch(void* const* d_in, const int* in_sizes, int n_in,
                              void* d_out, int out_size) {
    const float* qp    = (const float*)d_in[0];
    const float* codes = (const float*)d_in[1];
    const float* gpts  = (const float*)d_in[2];
    const float* eW1   = (const float*)d_in[3];
    const float* eb1   = (const float*)d_in[4];
    const float* eW2   = (const float*)d_in[5];
    const float* eb2   = (const float*)d_in[6];
    const float* cW    = (const float*)d_in[7];
    const float* cb    = (const float*)d_in[8];
    const float* fcW   = (const float*)d_in[9];
    const float* fcb   = (const float*)d_in[10];
    const float* nW1   = (const float*)d_in[11];
    const float* nb1   = (const float*)d_in[12];
    const float* nW2   = (const float*)d_in[13];
    const float* nb2   = (const float*)d_in[14];
    const int*   eidx  = (const int*)d_in[15];
    float* out = (float*)d_out;

    static bool attr_done = false;
    if (!attr_done) {
        cudaFuncSetAttribute(edge_mma_kernel<1>,
                             cudaFuncAttributeMaxDynamicSharedMemorySize, EDGE_SMEM);
        cudaFuncSetAttribute(edge_mma_kernel<TFIN>,
                             cudaFuncAttributeMaxDynamicSharedMemorySize, EDGE_SMEM);
        attr_done = true;
    }

    init_kernel<<<(NPTS * HDIM + 255) / 256, 256>>>(qp, codes);
    w2t_kernel<<<(4 * HDIM * HDIM + 255) / 256, 256>>>(eW2);

    for (int L = 0; L < 4; ++L) {
        proj_kernel<<<NNODES / 16, 128>>>(eW1, L);
        if (L < 3) {
            edge_mma_kernel<1><<<NPTS / 4, 256, EDGE_SMEM>>>(
                eidx, gpts, eW1, eb1, eb2, cW + L * HDIM, cb + L, qp, nullptr, L);
            node_kernel<<<NNODES / 16, 128>>>(nW1, nb1, nW2, nb2, L);
        } else {
            edge_mma_kernel<TFIN><<<NPTS / 4, 256, EDGE_SMEM>>>(
                eidx, gpts, eW1, eb1, eb2, fcW, fcb, qp, out, L);
        }
    }
}

// round 8
// speedup vs baseline: 2.0795x; 1.0492x over previous
#include <cuda_runtime.h>
#include <math.h>
#include <stdint.h>

#define NPTS   16384
#define NGRID  4096
#define NNODES 20480
#define GPTS   512
#define HDIM   128
#define DEG    16
#define TFIN   5

// ---------------- scratch (device globals, no allocation) ----------------
__device__ float g_xq[NPTS * 3];
__device__ float g_hq[NPTS * HDIM];
__device__ float g_hg[NGRID * HDIM];
__device__ float g_P[NGRID * HDIM];
__device__ float g_Q[NPTS * HDIM];
__device__ float g_summ[NPTS * HDIM];
__device__ float g_W2F[4 * HDIM * HDIM];   // W2^T per layer in MMA fragment layout

__device__ __forceinline__ float silu_f(float x) {
    return __fdividef(x, 1.0f + __expf(-x));
}
__device__ __forceinline__ float4 ldg4(const float* p) {
    return __ldg((const float4*)p);
}
__device__ __forceinline__ float tf32r(float v) {
    uint32_t t; asm("cvt.rna.tf32.f32 %0, %1;" : "=r"(t) : "f"(v));
    return __uint_as_float(t);
}
__device__ __forceinline__ void mma_tf32(float* c, uint32_t a0, uint32_t a1,
                                         uint32_t a2, uint32_t a3,
                                         uint32_t b0, uint32_t b1) {
    asm volatile(
        "mma.sync.aligned.m16n8k8.row.col.f32.tf32.tf32.f32 "
        "{%0,%1,%2,%3}, {%4,%5,%6,%7}, {%8,%9}, {%0,%1,%2,%3};"
        : "+f"(c[0]), "+f"(c[1]), "+f"(c[2]), "+f"(c[3])
        : "r"(a0), "r"(a1), "r"(a2), "r"(a3), "r"(b0), "r"(b1));
}

// ---- 4x4 scalar tile helpers (proj / node kernels) ----
#define FMA_TILE(acc, a, b) do {                                             \
    acc[0].x = fmaf(a.x, b.x, acc[0].x); acc[0].y = fmaf(a.x, b.y, acc[0].y);\
    acc[0].z = fmaf(a.x, b.z, acc[0].z); acc[0].w = fmaf(a.x, b.w, acc[0].w);\
    acc[1].x = fmaf(a.y, b.x, acc[1].x); acc[1].y = fmaf(a.y, b.y, acc[1].y);\
    acc[1].z = fmaf(a.y, b.z, acc[1].z); acc[1].w = fmaf(a.y, b.w, acc[1].w);\
    acc[2].x = fmaf(a.z, b.x, acc[2].x); acc[2].y = fmaf(a.z, b.y, acc[2].y);\
    acc[2].z = fmaf(a.z, b.z, acc[2].z); acc[2].w = fmaf(a.z, b.w, acc[2].w);\
    acc[3].x = fmaf(a.w, b.x, acc[3].x); acc[3].y = fmaf(a.w, b.y, acc[3].y);\
    acc[3].z = fmaf(a.w, b.z, acc[3].z); acc[3].w = fmaf(a.w, b.w, acc[3].w);\
} while (0)
#define ZERO4(acc) do {                                                      \
    acc[0] = make_float4(0.f,0.f,0.f,0.f); acc[1] = make_float4(0.f,0.f,0.f,0.f); \
    acc[2] = make_float4(0.f,0.f,0.f,0.f); acc[3] = make_float4(0.f,0.f,0.f,0.f); \
} while (0)

// ---------------- init ----------------
__global__ void init_kernel(const float* __restrict__ qp, const float* __restrict__ codes) {
    int i = blockIdx.x * blockDim.x + threadIdx.x;
    if (i < NPTS * HDIM)  g_hq[i] = 0.0f;
    if (i < NGRID * HDIM) g_hg[i] = codes[i];
    if (i < NPTS * 3)     g_xq[i] = qp[i];
}

// ---------------- W2^T -> tf32 fragment layout (4 layers, once per launch) -------
// Fragment quad index layout: (((layer*16 + k8)*8 + ntpair)*32 + lane)*4 + j
//   nt = ntpair*2 + (j>>1); jk = j&1
//   n  = nt*8 + (lane>>2);  k = k8*8 + (lane&3) + jk*4
__global__ void w2f_kernel(const float* __restrict__ eW2) {
    int i = blockIdx.x * blockDim.x + threadIdx.x;
    if (i >= 4 * HDIM * HDIM) return;
    int layer = i >> 14;
    int rem = i & 16383;
    int q = rem >> 2, j = rem & 3;
    int k8 = q >> 8;
    int ntpair = (q >> 5) & 7;
    int lane = q & 31;
    int nt = ntpair * 2 + (j >> 1);
    int jk = j & 1;
    int n = nt * 8 + (lane >> 2);
    int k = k8 * 8 + (lane & 3) + jk * 4;
    g_W2F[i] = tf32r(eW2[layer * 16384 + k * HDIM + n]);
}

// ---------------- projections (validated R3 version) ----------------
#define PK 20
__global__ __launch_bounds__(128) void proj_kernel(const float* __restrict__ eW1, int layer) {
    __shared__ float sA[HDIM * PK];
    const int tid = threadIdx.x;
    const int j4 = (tid & 31) * 4;
    const int mq = tid >> 5;
    const int base = blockIdx.x * 16;
    const bool isq = (base < NPTS);
    const float* W = eW1 + (size_t)layer * 257 * HDIM + (isq ? 128 * HDIM : 0);

    #pragma unroll
    for (int n = 0; n < 16; ++n) {
        int r = base + n;
        float v = (r < NPTS) ? g_hq[r * HDIM + tid] : g_hg[(r - NPTS) * HDIM + tid];
        sA[tid * PK + n] = v;
    }
    __syncthreads();

    float4 acc[4]; ZERO4(acc);
    #pragma unroll 4
    for (int k = 0; k < HDIM; ++k) {
        float4 a = *(const float4*)(sA + k * PK + mq * 4);
        float4 b = ldg4(W + k * HDIM + j4);
        FMA_TILE(acc, a, b);
    }
    float* outp = isq ? g_Q : g_P;
    int obase = isq ? base : (base - NPTS);
    #pragma unroll
    for (int mi = 0; mi < 4; ++mi)
        *(float4*)(outp + (obase + mq * 4 + mi) * HDIM + j4) = acc[mi];
}

// ---------------- edge kernel: mma.sync tf32, 4 M-tiles of 64 edges per block ----
// dynamic smem layout (bytes):
#define OFF_T     0          // A tile / M tile: 64 x 132 fp32 = 33792
#define OFF_B     33792      // W2F staged (fragment layout): 65536
#define OFF_GIDX  99328
#define OFF_DIST  99584
#define OFF_DX    99840
#define OFF_DY    100096
#define OFF_DZ    100352
#define OFF_CM    100608
#define OFF_B2    100864     // 512
#define OFF_B1    101376     // 512
#define OFF_WD    101888     // 512
#define OFF_FC    102400     // up to 128*5*4 = 2560
#define OFF_COEF  104960     // up to 64*5*4 = 1280
#define EDGE_SMEM 106496

template <int TOUT>
__global__ __launch_bounds__(256) void edge_mma_kernel(
    const int*   __restrict__ erow,
    const float* __restrict__ gpts,
    const float* __restrict__ eW1, const float* __restrict__ eb1,
    const float* __restrict__ eb2,
    const float* __restrict__ coefW, const float* __restrict__ coefB,
    const float* __restrict__ qpts, float* __restrict__ out, int layer)
{
    extern __shared__ char sb[];
    float* sT    = (float*)(sb + OFF_T);     // A, later reused as M
    float* sBf   = (float*)(sb + OFF_B);     // B fragments
    int*   sGidx = (int*)  (sb + OFF_GIDX);
    float* sDist = (float*)(sb + OFF_DIST);
    float* sDx   = (float*)(sb + OFF_DX);
    float* sDy   = (float*)(sb + OFF_DY);
    float* sDz   = (float*)(sb + OFF_DZ);
    float* sCm   = (float*)(sb + OFF_CM);
    float* sB2   = (float*)(sb + OFF_B2);
    float* sB1   = (float*)(sb + OFF_B1);
    float* sWd   = (float*)(sb + OFF_WD);
    float* sFc   = (float*)(sb + OFF_FC);
    float* sCoef = (float*)(sb + OFF_COEF);

    const int tid = threadIdx.x;
    const int wid = tid >> 5;
    const int lane = tid & 31;
    const float* W1L = eW1 + (size_t)layer * 257 * HDIM;

    // stage B (fragment layout, linear 64KB) + constants — once per block
    {
        const float4* src = (const float4*)(g_W2F + layer * 16384);
        float4* dst = (float4*)sBf;
        #pragma unroll
        for (int i = 0; i < 16; ++i) dst[tid + i * 256] = src[tid + i * 256];
    }
    if (tid < 128) {
        sB2[tid] = eb2[layer * HDIM + tid];
        sB1[tid] = eb1[layer * HDIM + tid];
        sWd[tid] = W1L[256 * HDIM + tid];
        #pragma unroll
        for (int t = 0; t < TOUT; ++t) sFc[tid * TOUT + t] = coefW[tid * TOUT + t];
    }
    __syncthreads();

    for (int tile = 0; tile < 4; ++tile) {
        const int bq4 = blockIdx.x * 16 + tile * 4;

        // geometry for 64 edges
        if (tid < 64) {
            int e = tid;
            int q = bq4 + (e >> 4);
            int rv = erow[q * DEG + (e & 15)];
            int gidx = rv - NPTS;
            int gl = gidx & (GPTS - 1);
            float rx = gpts[gl * 3 + 0] - g_xq[q * 3 + 0];
            float ry = gpts[gl * 3 + 1] - g_xq[q * 3 + 1];
            float rz = gpts[gl * 3 + 2] - g_xq[q * 3 + 2];
            float d = sqrtf(rx * rx + ry * ry + rz * rz);
            float inv = 1.0f / (d + 1e-8f);
            sGidx[e] = gidx; sDist[e] = d;
            sDx[e] = rx * inv; sDy[e] = ry * inv; sDz[e] = rz * inv;
            float cm = 0.5f * (__cosf(d * (float)(M_PI / 10.0)) + 1.0f);
            sCm[e] = (d <= 10.0f) ? cm : 0.0f;
        }
        __syncthreads();

        // stage 1: A[e][k] = tf32(silu(Q[q][k] + P[gidx][k] + dist*wd[k] + b1[k]))
        #pragma unroll
        for (int it = 0; it < 8; ++it) {
            int idx = tid + it * 256;
            int e = idx >> 5;
            int k4 = (idx & 31) * 4;
            int q = bq4 + (e >> 4);
            float4 Qv = ldg4(g_Q + q * HDIM + k4);
            float4 Pv = ldg4(g_P + sGidx[e] * HDIM + k4);
            float4 wd = *(const float4*)(sWd + k4);
            float4 b1 = *(const float4*)(sB1 + k4);
            float dd = sDist[e];
            float4 r;
            r.x = tf32r(silu_f(Qv.x + Pv.x + dd * wd.x + b1.x));
            r.y = tf32r(silu_f(Qv.y + Pv.y + dd * wd.y + b1.y));
            r.z = tf32r(silu_f(Qv.z + Pv.z + dd * wd.z + b1.z));
            r.w = tf32r(silu_f(Qv.w + Pv.w + dd * wd.w + b1.w));
            *(float4*)(sT + e * 132 + k4) = r;
        }
        __syncthreads();

        // mma: warp grid 4(m) x 2(n); warp tile 16 rows x 64 cols
        const int mw = wid & 3;
        const int nw = wid >> 2;
        float c[8][4];
        #pragma unroll
        for (int nt = 0; nt < 8; ++nt)
            #pragma unroll
            for (int i = 0; i < 4; ++i) c[nt][i] = 0.0f;

        const int arow = mw * 16 + (lane >> 2);
        const int kl   = lane & 3;
        #pragma unroll
        for (int k8 = 0; k8 < 16; ++k8) {
            int kc = k8 * 8 + kl;
            uint32_t a0 = __float_as_uint(sT[arow * 132 + kc]);
            uint32_t a1 = __float_as_uint(sT[(arow + 8) * 132 + kc]);
            uint32_t a2 = __float_as_uint(sT[arow * 132 + kc + 4]);
            uint32_t a3 = __float_as_uint(sT[(arow + 8) * 132 + kc + 4]);
            const float4* bbase = (const float4*)sBf + (k8 * 8 + nw * 4) * 32 + lane;
            #pragma unroll
            for (int p = 0; p < 4; ++p) {
                float4 bq = bbase[p * 32];
                mma_tf32(c[2 * p],     a0, a1, a2, a3,
                         __float_as_uint(bq.x), __float_as_uint(bq.y));
                mma_tf32(c[2 * p + 1], a0, a1, a2, a3,
                         __float_as_uint(bq.z), __float_as_uint(bq.w));
            }
        }
        __syncthreads();   // all warps done reading sT (A)

        // epilogue: M[e][j] = silu(D + b2[j]) * Cm[e], into sT (reused as sM)
        {
            const int r0 = mw * 16 + (lane >> 2);
            const int r1 = r0 + 8;
            const float cm0 = sCm[r0], cm1 = sCm[r1];
            #pragma unroll
            for (int nt = 0; nt < 8; ++nt) {
                int c0 = nw * 64 + nt * 8 + 2 * (lane & 3);
                float bz0 = sB2[c0], bz1 = sB2[c0 + 1];
                sT[r0 * 132 + c0]     = silu_f(c[nt][0] + bz0) * cm0;
                sT[r0 * 132 + c0 + 1] = silu_f(c[nt][1] + bz1) * cm0;
                sT[r1 * 132 + c0]     = silu_f(c[nt][2] + bz0) * cm1;
                sT[r1 * 132 + c0 + 1] = silu_f(c[nt][3] + bz1) * cm1;
            }
        }
        __syncthreads();

        // m_aggr (layers 0..2)
        if (TOUT == 1) {
            #pragma unroll
            for (int it = 0; it < 2; ++it) {
                int idx = tid + it * 256;
                int q = idx >> 7;
                int j = idx & 127;
                float s = 0.0f;
                #pragma unroll
                for (int e = 0; e < DEG; ++e) s += sT[(q * DEG + e) * 132 + j];
                g_summ[(bq4 + q) * HDIM + j] = s * (1.0f / DEG);
            }
        }

        // coef: 64 edges, 4 threads/edge
        {
            int e = tid >> 2, part = tid & 3;
            float acc[TOUT];
            #pragma unroll
            for (int t = 0; t < TOUT; ++t) acc[t] = 0.0f;
            const float* mr = sT + e * 132 + part * 32;
            #pragma unroll 8
            for (int i = 0; i < 32; ++i) {
                float mv = mr[i];
                int j = part * 32 + i;
                #pragma unroll
                for (int t = 0; t < TOUT; ++t) acc[t] = fmaf(mv, sFc[j * TOUT + t], acc[t]);
            }
            #pragma unroll
            for (int t = 0; t < TOUT; ++t) {
                float v = acc[t];
                v += __shfl_down_sync(0xFFFFFFFFu, v, 2);
                v += __shfl_down_sync(0xFFFFFFFFu, v, 1);
                if (part == 0) sCoef[e * TOUT + t] = v + __ldg(&coefB[t]);
            }
        }
        __syncthreads();

        // final reduction over 16 edges per query
        if (TOUT == 1) {
            if (tid < 12) {
                int q = tid / 3, d = tid % 3;
                const float* dirp = (d == 0) ? sDx : (d == 1) ? sDy : sDz;
                float s = 0.0f;
                #pragma unroll
                for (int e = 0; e < DEG; ++e) s += sCoef[q * DEG + e] * dirp[q * DEG + e];
                g_xq[(bq4 + q) * 3 + d] += s * (1.0f / DEG);
            }
        } else {
            if (tid < 4 * TOUT * 3) {
                int q = tid / (TOUT * 3);
                int r = tid % (TOUT * 3);
                int t = r / 3, d = r % 3;
                const float* dirp = (d == 0) ? sDx : (d == 1) ? sDy : sDz;
                float s = 0.0f;
                #pragma unroll
                for (int e = 0; e < DEG; ++e)
                    s += sCoef[(q * DEG + e) * TOUT + t] * dirp[q * DEG + e];
                int gq = bq4 + q;
                out[(gq * TFIN + t) * 3 + d] =
                    (g_xq[gq * 3 + d] - qpts[gq * 3 + d]) + s * (1.0f / DEG);
            }
        }
        __syncthreads();   // protect geometry/sT before next tile
    }
}

// ---------------- node kernel (validated R3 version) ----------------
#define SP 20
__global__ __launch_bounds__(128) void node_kernel(
    const float* __restrict__ nW1, const float* __restrict__ nb1,
    const float* __restrict__ nW2, const float* __restrict__ nb2, int layer)
{
    __shared__ float sIn[256 * SP];
    __shared__ float sU[HDIM * SP];
    const int tid = threadIdx.x;
    const int j4 = (tid & 31) * 4;
    const int mq = tid >> 5;
    const int base = blockIdx.x * 16;
    const float* W1 = nW1 + (size_t)layer * 256 * HDIM;
    const float* W2 = nW2 + (size_t)layer * HDIM * HDIM;
    const float4 bb1 = ldg4(nb1 + layer * HDIM + j4);
    const float4 bb2 = ldg4(nb2 + layer * HDIM + j4);

    #pragma unroll
    for (int n = 0; n < 16; ++n) {
        int node = base + n;
        float hv, mv;
        if (node < NPTS) { hv = g_hq[node * HDIM + tid]; mv = g_summ[node * HDIM + tid]; }
        else             { hv = g_hg[(node - NPTS) * HDIM + tid]; mv = 0.0f; }
        sIn[tid * SP + n] = hv;
        sIn[(128 + tid) * SP + n] = mv;
    }
    __syncthreads();

    float4 acc[4]; ZERO4(acc);
    #pragma unroll 4
    for (int k = 0; k < 256; ++k) {
        float4 a = *(const float4*)(sIn + k * SP + mq * 4);
        float4 b = ldg4(W1 + k * HDIM + j4);
        FMA_TILE(acc, a, b);
    }
    {
        float4 cc;
        cc = make_float4(silu_f(acc[0].x + bb1.x), silu_f(acc[1].x + bb1.x),
                         silu_f(acc[2].x + bb1.x), silu_f(acc[3].x + bb1.x));
        *(float4*)(sU + (j4 + 0) * SP + mq * 4) = cc;
        cc = make_float4(silu_f(acc[0].y + bb1.y), silu_f(acc[1].y + bb1.y),
                         silu_f(acc[2].y + bb1.y), silu_f(acc[3].y + bb1.y));
        *(float4*)(sU + (j4 + 1) * SP + mq * 4) = cc;
        cc = make_float4(silu_f(acc[0].z + bb1.z), silu_f(acc[1].z + bb1.z),
                         silu_f(acc[2].z + bb1.z), silu_f(acc[3].z + bb1.z));
        *(float4*)(sU + (j4 + 2) * SP + mq * 4) = cc;
        cc = make_float4(silu_f(acc[0].w + bb1.w), silu_f(acc[1].w + bb1.w),
                         silu_f(acc[2].w + bb1.w), silu_f(acc[3].w + bb1.w));
        *(float4*)(sU + (j4 + 3) * SP + mq * 4) = cc;
    }
    __syncthreads();

    ZERO4(acc);
    #pragma unroll 4
    for (int k = 0; k < HDIM; ++k) {
        float4 a = *(const float4*)(sU + k * SP + mq * 4);
        float4 b = ldg4(W2 + k * HDIM + j4);
        FMA_TILE(acc, a, b);
    }
    #pragma unroll
    for (int mi = 0; mi < 4; ++mi) {
        int node = base + mq * 4 + mi;
        float* hp = (node < NPTS) ? (g_hq + node * HDIM) : (g_hg + (node - NPTS) * HDIM);
        float4 hold = *(const float4*)(hp + j4);
        float4 o;
        o.x = hold.x + acc[mi].x + bb2.x;
        o.y = hold.y + acc[mi].y + bb2.y;
        o.z = hold.z + acc[mi].z + bb2.z;
        o.w = hold.w + acc[mi].w + bb2.w;
        *(float4*)(hp + j4) = o;
    }
}

// ---------------- launch ----------------
extern "C" void kernel_launch(void* const* d_in, const int* in_sizes, int n_in,
                              void* d_out, int out_size) {
    const float* qp    = (const float*)d_in[0];
    const float* codes = (const float*)d_in[1];
    const float* gpts  = (const float*)d_in[2];
    const float* eW1   = (const float*)d_in[3];
    const float* eb1   = (const float*)d_in[4];
    const float* eW2   = (const float*)d_in[5];
    const float* eb2   = (const float*)d_in[6];
    const float* cW    = (const float*)d_in[7];
    const float* cb    = (const float*)d_in[8];
    const float* fcW   = (const float*)d_in[9];
    const float* fcb   = (const float*)d_in[10];
    const float* nW1   = (const float*)d_in[11];
    const float* nb1   = (const float*)d_in[12];
    const float* nW2   = (const float*)d_in[13];
    const float* nb2   = (const float*)d_in[14];
    const int*   eidx  = (const int*)d_in[15];
    float* out = (float*)d_out;

    static bool attr_done = false;
    if (!attr_done) {
        cudaFuncSetAttribute(edge_mma_kernel<1>,
                             cudaFuncAttributeMaxDynamicSharedMemorySize, EDGE_SMEM);
        cudaFuncSetAttribute(edge_mma_kernel<TFIN>,
                             cudaFuncAttributeMaxDynamicSharedMemorySize, EDGE_SMEM);
        attr_done = true;
    }

    init_kernel<<<(NPTS * HDIM + 255) / 256, 256>>>(qp, codes);
    w2f_kernel<<<(4 * HDIM * HDIM + 255) / 256, 256>>>(eW2);

    for (int L = 0; L < 4; ++L) {
        proj_kernel<<<NNODES / 16, 128>>>(eW1, L);
        if (L < 3) {
            edge_mma_kernel<1><<<NPTS / 16, 256, EDGE_SMEM>>>(
                eidx, gpts, eW1, eb1, eb2, cW + L * HDIM, cb + L, qp, nullptr, L);
            node_kernel<<<NNODES / 16, 128>>>(nW1, nb1, nW2, nb2, L);
        } else {
            edge_mma_kernel<TFIN><<<NPTS / 16, 256, EDGE_SMEM>>>(
                eidx, gpts, eW1, eb1, eb2, fcW, fcb, qp, out, L);
        }
    }
}

// round 10
// speedup vs baseline: 3.6834x; 1.7713x over previous
#include <cuda_runtime.h>
#include <math.h>
#include <stdint.h>

#define NPTS   16384
#define NGRID  4096
#define NNODES 20480
#define GPTS   512
#define HDIM   128
#define DEG    16
#define TFIN   5

// ---------------- scratch (device globals, no allocation) ----------------
__device__ float g_xq[NPTS * 3];
__device__ float g_hq[NPTS * HDIM];
__device__ float g_hg[NGRID * HDIM];
__device__ float g_P[NGRID * HDIM];
__device__ float g_Q[NPTS * HDIM];
__device__ float g_summ[NPTS * HDIM];
__device__ float g_W2F[4 * 128 * 128];   // edge W2  fragments (tf32)
__device__ float g_W1F[4 * 256 * 128];   // node W1  fragments (tf32)
__device__ float g_WnF[4 * 128 * 128];   // node W2  fragments (tf32)

__device__ __forceinline__ float silu_f(float x) {
    return __fdividef(x, 1.0f + __expf(-x));
}
__device__ __forceinline__ float4 ldg4(const float* p) {
    return __ldg((const float4*)p);
}
__device__ __forceinline__ float tf32r(float v) {
    uint32_t t; asm("cvt.rna.tf32.f32 %0, %1;" : "=r"(t) : "f"(v));
    return __uint_as_float(t);
}
__device__ __forceinline__ void mma_tf32(float* c, const uint32_t* a,
                                         uint32_t b0, uint32_t b1) {
    asm volatile(
        "mma.sync.aligned.m16n8k8.row.col.f32.tf32.tf32.f32 "
        "{%0,%1,%2,%3}, {%4,%5,%6,%7}, {%8,%9}, {%0,%1,%2,%3};"
        : "+f"(c[0]), "+f"(c[1]), "+f"(c[2]), "+f"(c[3])
        : "r"(a[0]), "r"(a[1]), "r"(a[2]), "r"(a[3]), "r"(b0), "r"(b1));
}

// ---- 4x4 scalar tile helpers (proj kernel) ----
#define FMA_TILE(acc, a, b) do {                                             \
    acc[0].x = fmaf(a.x, b.x, acc[0].x); acc[0].y = fmaf(a.x, b.y, acc[0].y);\
    acc[0].z = fmaf(a.x, b.z, acc[0].z); acc[0].w = fmaf(a.x, b.w, acc[0].w);\
    acc[1].x = fmaf(a.y, b.x, acc[1].x); acc[1].y = fmaf(a.y, b.y, acc[1].y);\
    acc[1].z = fmaf(a.y, b.z, acc[1].z); acc[1].w = fmaf(a.y, b.w, acc[1].w);\
    acc[2].x = fmaf(a.z, b.x, acc[2].x); acc[2].y = fmaf(a.z, b.y, acc[2].y);\
    acc[2].z = fmaf(a.z, b.z, acc[2].z); acc[2].w = fmaf(a.z, b.w, acc[2].w);\
    acc[3].x = fmaf(a.w, b.x, acc[3].x); acc[3].y = fmaf(a.w, b.y, acc[3].y);\
    acc[3].z = fmaf(a.w, b.z, acc[3].z); acc[3].w = fmaf(a.w, b.w, acc[3].w);\
} while (0)
#define ZERO4(acc) do {                                                      \
    acc[0] = make_float4(0.f,0.f,0.f,0.f); acc[1] = make_float4(0.f,0.f,0.f,0.f); \
    acc[2] = make_float4(0.f,0.f,0.f,0.f); acc[3] = make_float4(0.f,0.f,0.f,0.f); \
} while (0)

// ---------------- init ----------------
__global__ void init_kernel(const float* __restrict__ qp, const float* __restrict__ codes) {
    int i = blockIdx.x * blockDim.x + threadIdx.x;
    if (i < NPTS * HDIM)  g_hq[i] = 0.0f;
    if (i < NGRID * HDIM) g_hg[i] = codes[i];
    if (i < NPTS * 3)     g_xq[i] = qp[i];
}

// ---------------- generic B fragment packer (N=128) ----------------
// quad idx = ((k8*8 + ntpair)*32 + lane), j=0..3
//   nt = ntpair*2 + (j>>1); n = nt*8 + (lane>>2); k = k8*8 + (lane&3) + (j&1)*4
// src: [4 layers][K][128] row-major
__global__ void pack_kernel(const float* __restrict__ src, float* __restrict__ dst, int K) {
    int i = blockIdx.x * blockDim.x + threadIdx.x;
    int tot = 4 * K * 128;
    if (i >= tot) return;
    int layer = i / (K * 128);
    int rem = i % (K * 128);
    int quad = rem >> 2, j = rem & 3;
    int lane = quad & 31;
    int ntpair = (quad >> 5) & 7;
    int k8 = quad >> 8;
    int nt = ntpair * 2 + (j >> 1);
    int n = nt * 8 + (lane >> 2);
    int k = k8 * 8 + (lane & 3) + ((j & 1) << 2);
    dst[i] = tf32r(src[layer * K * 128 + k * 128 + n]);
}

// ---------------- projections (validated R3 version) ----------------
#define PK 20
__global__ __launch_bounds__(128) void proj_kernel(const float* __restrict__ eW1, int layer) {
    __shared__ float sA[HDIM * PK];
    const int tid = threadIdx.x;
    const int j4 = (tid & 31) * 4;
    const int mq = tid >> 5;
    const int base = blockIdx.x * 16;
    const bool isq = (base < NPTS);
    const float* W = eW1 + (size_t)layer * 257 * HDIM + (isq ? 128 * HDIM : 0);

    #pragma unroll
    for (int n = 0; n < 16; ++n) {
        int r = base + n;
        float v = (r < NPTS) ? g_hq[r * HDIM + tid] : g_hg[(r - NPTS) * HDIM + tid];
        sA[tid * PK + n] = v;
    }
    __syncthreads();

    float4 acc[4]; ZERO4(acc);
    #pragma unroll 4
    for (int k = 0; k < HDIM; ++k) {
        float4 a = *(const float4*)(sA + k * PK + mq * 4);
        float4 b = ldg4(W + k * HDIM + j4);
        FMA_TILE(acc, a, b);
    }
    float* outp = isq ? g_Q : g_P;
    int obase = isq ? base : (base - NPTS);
    #pragma unroll
    for (int mi = 0; mi < 4; ++mi)
        *(float4*)(outp + (obase + mq * 4 + mi) * HDIM + j4) = acc[mi];
}

// ---------------- edge kernel: tf32 mma, 64 edges (4 queries) per block ----------
template <int TOUT>
__global__ __launch_bounds__(256) void edge_mma_kernel(
    const int*   __restrict__ erow,
    const float* __restrict__ gpts,
    const float* __restrict__ eW1, const float* __restrict__ eb1,
    const float* __restrict__ eb2,
    const float* __restrict__ coefW, const float* __restrict__ coefB,
    const float* __restrict__ qpts, float* __restrict__ out, int layer)
{
    __shared__ float sT[64 * 132];     // A, later reused as M
    __shared__ int   sGidx[64];
    __shared__ float sDist[64], sDx[64], sDy[64], sDz[64], sCm[64];
    __shared__ float sB2[128], sB1[128], sWd[128];
    __shared__ float sFc[128 * TOUT];
    __shared__ float sCoef[64 * TOUT];

    const int tid = threadIdx.x;
    const int wid = tid >> 5;
    const int lane = tid & 31;
    const int bq4 = blockIdx.x * 4;
    const float* W1L = eW1 + (size_t)layer * 257 * HDIM;

    if (tid < 128) {
        sB2[tid] = eb2[layer * HDIM + tid];
        sB1[tid] = eb1[layer * HDIM + tid];
        sWd[tid] = W1L[256 * HDIM + tid];
        #pragma unroll
        for (int t = 0; t < TOUT; ++t) sFc[tid * TOUT + t] = coefW[tid * TOUT + t];
    }
    if (tid < 64) {
        int e = tid;
        int q = bq4 + (e >> 4);
        int rv = erow[q * DEG + (e & 15)];
        int gidx = rv - NPTS;
        int gl = gidx & (GPTS - 1);
        float rx = gpts[gl * 3 + 0] - g_xq[q * 3 + 0];
        float ry = gpts[gl * 3 + 1] - g_xq[q * 3 + 1];
        float rz = gpts[gl * 3 + 2] - g_xq[q * 3 + 2];
        float d = sqrtf(rx * rx + ry * ry + rz * rz);
        float inv = 1.0f / (d + 1e-8f);
        sGidx[e] = gidx; sDist[e] = d;
        sDx[e] = rx * inv; sDy[e] = ry * inv; sDz[e] = rz * inv;
        float cm = 0.5f * (__cosf(d * (float)(M_PI / 10.0)) + 1.0f);
        sCm[e] = (d <= 10.0f) ? cm : 0.0f;
    }
    __syncthreads();

    // stage 1: A[e][k] = tf32(silu(Q[q][k] + P[gidx][k] + dist*wd[k] + b1[k]))
    #pragma unroll
    for (int it = 0; it < 8; ++it) {
        int idx = tid + it * 256;
        int e = idx >> 5;
        int k4 = (idx & 31) * 4;
        int q = bq4 + (e >> 4);
        float4 Qv = ldg4(g_Q + q * HDIM + k4);
        float4 Pv = ldg4(g_P + sGidx[e] * HDIM + k4);
        float4 wd = *(const float4*)(sWd + k4);
        float4 b1 = *(const float4*)(sB1 + k4);
        float dd = sDist[e];
        float4 r;
        r.x = tf32r(silu_f(Qv.x + Pv.x + dd * wd.x + b1.x));
        r.y = tf32r(silu_f(Qv.y + Pv.y + dd * wd.y + b1.y));
        r.z = tf32r(silu_f(Qv.z + Pv.z + dd * wd.z + b1.z));
        r.w = tf32r(silu_f(Qv.w + Pv.w + dd * wd.w + b1.w));
        *(float4*)(sT + e * 132 + k4) = r;
    }
    __syncthreads();

    // mma: warp grid 2(m) x 4(n); warp tile 32 rows x 32 cols
    const int mw = wid & 1;
    const int nw = wid >> 1;
    const int r4 = lane >> 2;
    const int kl = lane & 3;
    float c[2][4][4];
    #pragma unroll
    for (int s = 0; s < 2; ++s)
        #pragma unroll
        for (int ln = 0; ln < 4; ++ln)
            #pragma unroll
            for (int i = 0; i < 4; ++i) c[s][ln][i] = 0.0f;

    const float4* bfrag = (const float4*)(g_W2F + layer * 16384);
    float4 bq0 = __ldg(&bfrag[(nw * 2 + 0) * 32 + lane]);
    float4 bq1 = __ldg(&bfrag[(nw * 2 + 1) * 32 + lane]);
    #pragma unroll
    for (int k8 = 0; k8 < 16; ++k8) {
        float4 nb0, nb1;
        if (k8 < 15) {
            nb0 = __ldg(&bfrag[((k8 + 1) * 8 + nw * 2 + 0) * 32 + lane]);
            nb1 = __ldg(&bfrag[((k8 + 1) * 8 + nw * 2 + 1) * 32 + lane]);
        }
        int kc = k8 * 8 + kl;
        uint32_t a[2][4];
        #pragma unroll
        for (int s = 0; s < 2; ++s) {
            int rb = mw * 32 + s * 16 + r4;
            a[s][0] = __float_as_uint(sT[rb * 132 + kc]);
            a[s][1] = __float_as_uint(sT[(rb + 8) * 132 + kc]);
            a[s][2] = __float_as_uint(sT[rb * 132 + kc + 4]);
            a[s][3] = __float_as_uint(sT[(rb + 8) * 132 + kc + 4]);
        }
        #pragma unroll
        for (int s = 0; s < 2; ++s) {
            mma_tf32(c[s][0], a[s], __float_as_uint(bq0.x), __float_as_uint(bq0.y));
            mma_tf32(c[s][1], a[s], __float_as_uint(bq0.z), __float_as_uint(bq0.w));
            mma_tf32(c[s][2], a[s], __float_as_uint(bq1.x), __float_as_uint(bq1.y));
            mma_tf32(c[s][3], a[s], __float_as_uint(bq1.z), __float_as_uint(bq1.w));
        }
        bq0 = nb0; bq1 = nb1;
    }
    __syncthreads();   // all warps done reading sT (A)

    // epilogue: M[e][j] = silu(D + b2[j]) * Cm[e], into sT (reused as sM)
    #pragma unroll
    for (int s = 0; s < 2; ++s) {
        int r0 = mw * 32 + s * 16 + r4;
        int r1 = r0 + 8;
        float cm0 = sCm[r0], cm1 = sCm[r1];
        #pragma unroll
        for (int ln = 0; ln < 4; ++ln) {
            int c0 = nw * 32 + ln * 8 + 2 * kl;
            float bz0 = sB2[c0], bz1 = sB2[c0 + 1];
            *(float2*)(sT + r0 * 132 + c0) =
                make_float2(silu_f(c[s][ln][0] + bz0) * cm0, silu_f(c[s][ln][1] + bz1) * cm0);
            *(float2*)(sT + r1 * 132 + c0) =
                make_float2(silu_f(c[s][ln][2] + bz0) * cm1, silu_f(c[s][ln][3] + bz1) * cm1);
        }
    }
    __syncthreads();

    // m_aggr (layers 0..2)
    if (TOUT == 1) {
        #pragma unroll
        for (int it = 0; it < 2; ++it) {
            int idx = tid + it * 256;
            int q = idx >> 7;
            int j = idx & 127;
            float s = 0.0f;
            #pragma unroll
            for (int e = 0; e < DEG; ++e) s += sT[(q * DEG + e) * 132 + j];
            g_summ[(bq4 + q) * HDIM + j] = s * (1.0f / DEG);
        }
    }

    // coef: 64 edges, 4 threads/edge (interleaved cols -> conflict-free)
    {
        int e = tid >> 2, part = tid & 3;
        float acc[TOUT];
        #pragma unroll
        for (int t = 0; t < TOUT; ++t) acc[t] = 0.0f;
        const float* mr = sT + e * 132;
        #pragma unroll 8
        for (int i = 0; i < 32; ++i) {
            int j = i * 4 + part;
            float mv = mr[j];
            #pragma unroll
            for (int t = 0; t < TOUT; ++t) acc[t] = fmaf(mv, sFc[j * TOUT + t], acc[t]);
        }
        #pragma unroll
        for (int t = 0; t < TOUT; ++t) {
            float v = acc[t];
            v += __shfl_down_sync(0xFFFFFFFFu, v, 2);
            v += __shfl_down_sync(0xFFFFFFFFu, v, 1);
            if (part == 0) sCoef[e * TOUT + t] = v + __ldg(&coefB[t]);
        }
    }
    __syncthreads();

    // final reduction over 16 edges per query
    if (TOUT == 1) {
        if (tid < 12) {
            int q = tid / 3, d = tid % 3;
            const float* dirp = (d == 0) ? sDx : (d == 1) ? sDy : sDz;
            float s = 0.0f;
            #pragma unroll
            for (int e = 0; e < DEG; ++e) s += sCoef[q * DEG + e] * dirp[q * DEG + e];
            g_xq[(bq4 + q) * 3 + d] += s * (1.0f / DEG);
        }
    } else {
        if (tid < 4 * TOUT * 3) {
            int q = tid / (TOUT * 3);
            int r = tid % (TOUT * 3);
            int t = r / 3, d = r % 3;
            const float* dirp = (d == 0) ? sDx : (d == 1) ? sDy : sDz;
            float s = 0.0f;
            #pragma unroll
            for (int e = 0; e < DEG; ++e)
                s += sCoef[(q * DEG + e) * TOUT + t] * dirp[q * DEG + e];
            int gq = bq4 + q;
            out[(gq * TFIN + t) * 3 + d] =
                (g_xq[gq * 3 + d] - qpts[gq * 3 + d]) + s * (1.0f / DEG);
        }
    }
}

// ---------------- node kernel: tf32 mma, 64 nodes per block ----------------
// dyn smem: sIn [64][260] floats = 66560B; sB1 128, sB2 128 floats
#define NODE_SMEM (66560 + 1024)

__global__ __launch_bounds__(256) void node_mma_kernel(
    const float* __restrict__ nb1_, const float* __restrict__ nb2_, int layer)
{
    extern __shared__ float sm[];
    float* sIn = sm;                 // A1 [64][260]; later U [64][132]
    float* sB1 = sm + 16640;
    float* sB2 = sB1 + 128;

    const int tid = threadIdx.x;
    const int wid = tid >> 5;
    const int lane = tid & 31;
    const int base = blockIdx.x * 64;
    const bool isq = (base < NPTS);
    const float* hsrc = isq ? (g_hq + base * HDIM) : (g_hg + (base - NPTS) * HDIM);
    float* hdst = isq ? (g_hq + base * HDIM) : (g_hg + (base - NPTS) * HDIM);

    if (tid < 128) {
        sB1[tid] = nb1_[layer * HDIM + tid];
        sB2[tid] = nb2_[layer * HDIM + tid];
    }

    // A-stage: In[row][0:128]=h, [128:256]=m_aggr (0 for grid), tf32-rounded
    #pragma unroll
    for (int it = 0; it < 16; ++it) {
        int idx = tid + it * 256;          // float4 units, 4096 total
        int row = idx >> 6;
        int c4 = (idx & 63) * 4;
        float4 v;
        if (c4 < 128) {
            v = ldg4(hsrc + row * HDIM + c4);
        } else if (isq) {
            v = ldg4(g_summ + (base + row) * HDIM + (c4 - 128));
        } else {
            v = make_float4(0.f, 0.f, 0.f, 0.f);
        }
        v.x = tf32r(v.x); v.y = tf32r(v.y); v.z = tf32r(v.z); v.w = tf32r(v.w);
        *(float4*)(sIn + row * 260 + c4) = v;
    }
    __syncthreads();

    const int mw = wid & 1;
    const int nw = wid >> 1;
    const int r4 = lane >> 2;
    const int kl = lane & 3;

    // GEMM1: [64x256] @ W1 -> 64x128
    float c[2][4][4];
    #pragma unroll
    for (int s = 0; s < 2; ++s)
        #pragma unroll
        for (int ln = 0; ln < 4; ++ln)
            #pragma unroll
            for (int i = 0; i < 4; ++i) c[s][ln][i] = 0.0f;
    {
        const float4* bfrag = (const float4*)(g_W1F + layer * 32768);
        float4 bq0 = __ldg(&bfrag[(nw * 2 + 0) * 32 + lane]);
        float4 bq1 = __ldg(&bfrag[(nw * 2 + 1) * 32 + lane]);
        #pragma unroll
        for (int k8 = 0; k8 < 32; ++k8) {
            float4 nb0, nb1;
            if (k8 < 31) {
                nb0 = __ldg(&bfrag[((k8 + 1) * 8 + nw * 2 + 0) * 32 + lane]);
                nb1 = __ldg(&bfrag[((k8 + 1) * 8 + nw * 2 + 1) * 32 + lane]);
            }
            int kc = k8 * 8 + kl;
            uint32_t a[2][4];
            #pragma unroll
            for (int s = 0; s < 2; ++s) {
                int rb = mw * 32 + s * 16 + r4;
                a[s][0] = __float_as_uint(sIn[rb * 260 + kc]);
                a[s][1] = __float_as_uint(sIn[(rb + 8) * 260 + kc]);
                a[s][2] = __float_as_uint(sIn[rb * 260 + kc + 4]);
                a[s][3] = __float_as_uint(sIn[(rb + 8) * 260 + kc + 4]);
            }
            #pragma unroll
            for (int s = 0; s < 2; ++s) {
                mma_tf32(c[s][0], a[s], __float_as_uint(bq0.x), __float_as_uint(bq0.y));
                mma_tf32(c[s][1], a[s], __float_as_uint(bq0.z), __float_as_uint(bq0.w));
                mma_tf32(c[s][2], a[s], __float_as_uint(bq1.x), __float_as_uint(bq1.y));
                mma_tf32(c[s][3], a[s], __float_as_uint(bq1.z), __float_as_uint(bq1.w));
            }
            bq0 = nb0; bq1 = nb1;
        }
    }
    __syncthreads();   // all warps done reading sIn (A1)

    // U = tf32(silu(acc + b1)), into sIn reused as [64][132]
    #pragma unroll
    for (int s = 0; s < 2; ++s) {
        int r0 = mw * 32 + s * 16 + r4;
        int r1 = r0 + 8;
        #pragma unroll
        for (int ln = 0; ln < 4; ++ln) {
            int c0 = nw * 32 + ln * 8 + 2 * kl;
            float bz0 = sB1[c0], bz1 = sB1[c0 + 1];
            *(float2*)(sIn + r0 * 132 + c0) =
                make_float2(tf32r(silu_f(c[s][ln][0] + bz0)), tf32r(silu_f(c[s][ln][1] + bz1)));
            *(float2*)(sIn + r1 * 132 + c0) =
                make_float2(tf32r(silu_f(c[s][ln][2] + bz0)), tf32r(silu_f(c[s][ln][3] + bz1)));
        }
    }
    __syncthreads();

    // GEMM2: U[64x128] @ W2 -> 64x128
    #pragma unroll
    for (int s = 0; s < 2; ++s)
        #pragma unroll
        for (int ln = 0; ln < 4; ++ln)
            #pragma unroll
            for (int i = 0; i < 4; ++i) c[s][ln][i] = 0.0f;
    {
        const float4* bfrag = (const float4*)(g_WnF + layer * 16384);
        float4 bq0 = __ldg(&bfrag[(nw * 2 + 0) * 32 + lane]);
        float4 bq1 = __ldg(&bfrag[(nw * 2 + 1) * 32 + lane]);
        #pragma unroll
        for (int k8 = 0; k8 < 16; ++k8) {
            float4 nb0, nb1;
            if (k8 < 15) {
                nb0 = __ldg(&bfrag[((k8 + 1) * 8 + nw * 2 + 0) * 32 + lane]);
                nb1 = __ldg(&bfrag[((k8 + 1) * 8 + nw * 2 + 1) * 32 + lane]);
            }
            int kc = k8 * 8 + kl;
            uint32_t a[2][4];
            #pragma unroll
            for (int s = 0; s < 2; ++s) {
                int rb = mw * 32 + s * 16 + r4;
                a[s][0] = __float_as_uint(sIn[rb * 132 + kc]);
                a[s][1] = __float_as_uint(sIn[(rb + 8) * 132 + kc]);
                a[s][2] = __float_as_uint(sIn[rb * 132 + kc + 4]);
                a[s][3] = __float_as_uint(sIn[(rb + 8) * 132 + kc + 4]);
            }
            #pragma unroll
            for (int s = 0; s < 2; ++s) {
                mma_tf32(c[s][0], a[s], __float_as_uint(bq0.x), __float_as_uint(bq0.y));
                mma_tf32(c[s][1], a[s], __float_as_uint(bq0.z), __float_as_uint(bq0.w));
                mma_tf32(c[s][2], a[s], __float_as_uint(bq1.x), __float_as_uint(bq1.y));
                mma_tf32(c[s][3], a[s], __float_as_uint(bq1.z), __float_as_uint(bq1.w));
            }
            bq0 = nb0; bq1 = nb1;
        }
    }

    // h += D + b2  (direct global read-modify-write, float2 per fragment pair)
    #pragma unroll
    for (int s = 0; s < 2; ++s) {
        int r0 = mw * 32 + s * 16 + r4;
        int r1 = r0 + 8;
        #pragma unroll
        for (int ln = 0; ln < 4; ++ln) {
            int c0 = nw * 32 + ln * 8 + 2 * kl;
            float bz0 = sB2[c0], bz1 = sB2[c0 + 1];
            float2 h0 = *(const float2*)(hdst + r0 * HDIM + c0);
            float2 h1 = *(const float2*)(hdst + r1 * HDIM + c0);
            *(float2*)(hdst + r0 * HDIM + c0) =
                make_float2(h0.x + c[s][ln][0] + bz0, h0.y + c[s][ln][1] + bz1);
            *(float2*)(hdst + r1 * HDIM + c0) =
                make_float2(h1.x + c[s][ln][2] + bz0, h1.y + c[s][ln][3] + bz1);
        }
    }
}

// ---------------- launch ----------------
extern "C" void kernel_launch(void* const* d_in, const int* in_sizes, int n_in,
                              void* d_out, int out_size) {
    const float* qp    = (const float*)d_in[0];
    const float* codes = (const float*)d_in[1];
    const float* gpts  = (const float*)d_in[2];
    const float* eW1   = (const float*)d_in[3];
    const float* eb1   = (const float*)d_in[4];
    const float* eW2   = (const float*)d_in[5];
    const float* eb2   = (const float*)d_in[6];
    const float* cW    = (const float*)d_in[7];
    const float* cb    = (const float*)d_in[8];
    const float* fcW   = (const float*)d_in[9];
    const float* fcb   = (const float*)d_in[10];
    const float* nW1   = (const float*)d_in[11];
    const float* nb1   = (const float*)d_in[12];
    const float* nW2   = (const float*)d_in[13];
    const float* nb2   = (const float*)d_in[14];
    const int*   eidx  = (const int*)d_in[15];
    float* out = (float*)d_out;

    static bool attr_done = false;
    if (!attr_done) {
        cudaFuncSetAttribute(node_mma_kernel,
                             cudaFuncAttributeMaxDynamicSharedMemorySize, NODE_SMEM);
        attr_done = true;
    }

    init_kernel<<<(NPTS * HDIM + 255) / 256, 256>>>(qp, codes);

    float* w2f; cudaGetSymbolAddress((void**)&w2f, g_W2F);
    float* w1f; cudaGetSymbolAddress((void**)&w1f, g_W1F);
    float* wnf; cudaGetSymbolAddress((void**)&wnf, g_WnF);
    pack_kernel<<<(4 * 128 * 128 + 255) / 256, 256>>>(eW2, w2f, 128);
    pack_kernel<<<(4 * 256 * 128 + 255) / 256, 256>>>(nW1, w1f, 256);
    pack_kernel<<<(4 * 128 * 128 + 255) / 256, 256>>>(nW2, wnf, 128);

    for (int L = 0; L < 4; ++L) {
        proj_kernel<<<NNODES / 16, 128>>>(eW1, L);
        if (L < 3) {
            edge_mma_kernel<1><<<NPTS / 4, 256>>>(
                eidx, gpts, eW1, eb1, eb2, cW + L * HDIM, cb + L, qp, nullptr, L);
            node_mma_kernel<<<NNODES / 64, 256, NODE_SMEM>>>(nb1, nb2, L);
        } else {
            edge_mma_kernel<TFIN><<<NPTS / 4, 256>>>(
                eidx, gpts, eW1, eb1, eb2, fcW, fcb, qp, out, L);
        }
    }
}

// round 12
// speedup vs baseline: 4.1858x; 1.1364x over previous
#include <cuda_runtime.h>
#include <math.h>
#include <stdint.h>

#define NPTS   16384
#define NGRID  4096
#define NNODES 20480
#define GPTS   512
#define HDIM   128
#define DEG    16
#define TFIN   5

// ---------------- scratch (device globals, no allocation) ----------------
__device__ float g_xq[NPTS * 3];
__device__ float g_hq[NPTS * HDIM];
__device__ float g_hg[NGRID * HDIM];
__device__ float g_P[NGRID * HDIM];
__device__ float g_Q[NPTS * HDIM];
__device__ float g_summ[NPTS * HDIM];
__device__ float g_W2F[4 * 128 * 128];   // edge W2  fragments (tf32)
__device__ float g_W1F[4 * 256 * 128];   // node W1  fragments (tf32)
__device__ float g_WnF[4 * 128 * 128];   // node W2  fragments (tf32)
__device__ float g_WqF[4 * 128 * 128];   // We1 query-half fragments (tf32)
__device__ float g_WgF[4 * 128 * 128];   // We1 grid-half  fragments (tf32)

__device__ __forceinline__ float silu_f(float x) {
    return __fdividef(x, 1.0f + __expf(-x));
}
__device__ __forceinline__ float4 ldg4(const float* p) {
    return __ldg((const float4*)p);
}
__device__ __forceinline__ float tf32r(float v) {
    uint32_t t; asm("cvt.rna.tf32.f32 %0, %1;" : "=r"(t) : "f"(v));
    return __uint_as_float(t);
}
__device__ __forceinline__ void mma_tf32(float* c, const uint32_t* a,
                                         uint32_t b0, uint32_t b1) {
    asm volatile(
        "mma.sync.aligned.m16n8k8.row.col.f32.tf32.tf32.f32 "
        "{%0,%1,%2,%3}, {%4,%5,%6,%7}, {%8,%9}, {%0,%1,%2,%3};"
        : "+f"(c[0]), "+f"(c[1]), "+f"(c[2]), "+f"(c[3])
        : "r"(a[0]), "r"(a[1]), "r"(a[2]), "r"(a[3]), "r"(b0), "r"(b1));
}

// ---- 4x4 scalar tile helpers (proj0 kernel) ----
#define FMA_TILE(acc, a, b) do {                                             \
    acc[0].x = fmaf(a.x, b.x, acc[0].x); acc[0].y = fmaf(a.x, b.y, acc[0].y);\
    acc[0].z = fmaf(a.x, b.z, acc[0].z); acc[0].w = fmaf(a.x, b.w, acc[0].w);\
    acc[1].x = fmaf(a.y, b.x, acc[1].x); acc[1].y = fmaf(a.y, b.y, acc[1].y);\
    acc[1].z = fmaf(a.y, b.z, acc[1].z); acc[1].w = fmaf(a.y, b.w, acc[1].w);\
    acc[2].x = fmaf(a.z, b.x, acc[2].x); acc[2].y = fmaf(a.z, b.y, acc[2].y);\
    acc[2].z = fmaf(a.z, b.z, acc[2].z); acc[2].w = fmaf(a.z, b.w, acc[2].w);\
    acc[3].x = fmaf(a.w, b.x, acc[3].x); acc[3].y = fmaf(a.w, b.y, acc[3].y);\
    acc[3].z = fmaf(a.w, b.z, acc[3].z); acc[3].w = fmaf(a.w, b.w, acc[3].w);\
} while (0)
#define ZERO4(acc) do {                                                      \
    acc[0] = make_float4(0.f,0.f,0.f,0.f); acc[1] = make_float4(0.f,0.f,0.f,0.f); \
    acc[2] = make_float4(0.f,0.f,0.f,0.f); acc[3] = make_float4(0.f,0.f,0.f,0.f); \
} while (0)

// ---------------- init ----------------
__global__ void init_kernel(const float* __restrict__ qp, const float* __restrict__ codes) {
    int i = blockIdx.x * blockDim.x + threadIdx.x;
    if (i < NPTS * HDIM)  { g_hq[i] = 0.0f; g_Q[i] = 0.0f; }  // Q0 = 0@W = 0
    if (i < NGRID * HDIM) g_hg[i] = codes[i];
    if (i < NPTS * 3)     g_xq[i] = qp[i];
}

// ---------------- generic B fragment packer (N=128, contiguous src) --------------
// quad idx = ((k8*8 + ntpair)*32 + lane), j=0..3
//   nt = ntpair*2 + (j>>1); n = nt*8 + (lane>>2); k = k8*8 + (lane&3) + (j&1)*4
__global__ void pack_kernel(const float* __restrict__ src, float* __restrict__ dst, int K) {
    int i = blockIdx.x * blockDim.x + threadIdx.x;
    int tot = 4 * K * 128;
    if (i >= tot) return;
    int layer = i / (K * 128);
    int rem = i % (K * 128);
    int quad = rem >> 2, j = rem & 3;
    int lane = quad & 31;
    int ntpair = (quad >> 5) & 7;
    int k8 = quad >> 8;
    int nt = ntpair * 2 + (j >> 1);
    int n = nt * 8 + (lane >> 2);
    int k = k8 * 8 + (lane & 3) + ((j & 1) << 2);
    dst[i] = tf32r(src[layer * K * 128 + k * 128 + n]);
}

// ---- We1 sub-matrix packer: src [4][257][128], take rows row_off..row_off+127 ----
__global__ void pack_w1_kernel(const float* __restrict__ src, float* __restrict__ dst,
                               int row_off) {
    int i = blockIdx.x * blockDim.x + threadIdx.x;
    if (i >= 4 * 128 * 128) return;
    int layer = i >> 14;
    int rem = i & 16383;
    int quad = rem >> 2, j = rem & 3;
    int lane = quad & 31;
    int ntpair = (quad >> 5) & 7;
    int k8 = quad >> 8;
    int nt = ntpair * 2 + (j >> 1);
    int n = nt * 8 + (lane >> 2);
    int k = k8 * 8 + (lane & 3) + ((j & 1) << 2);
    dst[i] = tf32r(src[(size_t)layer * 257 * 128 + (row_off + k) * 128 + n]);
}

// ---------------- proj0: grid nodes only, layer 0 (scalar, fp32) ----------------
#define PK 20
__global__ __launch_bounds__(128) void proj_kernel(const float* __restrict__ eW1) {
    __shared__ float sA[HDIM * PK];
    const int tid = threadIdx.x;
    const int j4 = (tid & 31) * 4;
    const int mq = tid >> 5;
    const int gbase = blockIdx.x * 16;           // grid-node index
    const float* W = eW1;                        // layer 0, rows 0:128 (grid half)

    #pragma unroll
    for (int n = 0; n < 16; ++n)
        sA[tid * PK + n] = g_hg[(gbase + n) * HDIM + tid];
    __syncthreads();

    float4 acc[4]; ZERO4(acc);
    #pragma unroll 4
    for (int k = 0; k < HDIM; ++k) {
        float4 a = *(const float4*)(sA + k * PK + mq * 4);
        float4 b = ldg4(W + k * HDIM + j4);
        FMA_TILE(acc, a, b);
    }
    #pragma unroll
    for (int mi = 0; mi < 4; ++mi)
        *(float4*)(g_P + (gbase + mq * 4 + mi) * HDIM + j4) = acc[mi];
}

// ---------------- edge kernel: tf32 mma, 64 edges (4 queries) per block ----------
template <int TOUT>
__global__ __launch_bounds__(256) void edge_mma_kernel(
    const int*   __restrict__ erow,
    const float* __restrict__ gpts,
    const float* __restrict__ eW1, const float* __restrict__ eb1,
    const float* __restrict__ eb2,
    const float* __restrict__ coefW, const float* __restrict__ coefB,
    const float* __restrict__ qpts, float* __restrict__ out, int layer)
{
    __shared__ float sT[64 * 132];     // A, later reused as M
    __shared__ int   sGidx[64];
    __shared__ float sDist[64], sDx[64], sDy[64], sDz[64], sCm[64];
    __shared__ float sB2[128], sB1[128], sWd[128];
    __shared__ float sFc[128 * TOUT];
    __shared__ float sCoef[64 * TOUT];

    const int tid = threadIdx.x;
    const int wid = tid >> 5;
    const int lane = tid & 31;
    const int bq4 = blockIdx.x * 4;
    const float* W1L = eW1 + (size_t)layer * 257 * HDIM;

    if (tid < 128) {
        sB2[tid] = eb2[layer * HDIM + tid];
        sB1[tid] = eb1[layer * HDIM + tid];
        sWd[tid] = W1L[256 * HDIM + tid];
        #pragma unroll
        for (int t = 0; t < TOUT; ++t) sFc[tid * TOUT + t] = coefW[tid * TOUT + t];
    }
    if (tid < 64) {
        int e = tid;
        int q = bq4 + (e >> 4);
        int rv = erow[q * DEG + (e & 15)];
        int gidx = rv - NPTS;
        int gl = gidx & (GPTS - 1);
        float rx = gpts[gl * 3 + 0] - g_xq[q * 3 + 0];
        float ry = gpts[gl * 3 + 1] - g_xq[q * 3 + 1];
        float rz = gpts[gl * 3 + 2] - g_xq[q * 3 + 2];
        float d = sqrtf(rx * rx + ry * ry + rz * rz);
        float inv = 1.0f / (d + 1e-8f);
        sGidx[e] = gidx; sDist[e] = d;
        sDx[e] = rx * inv; sDy[e] = ry * inv; sDz[e] = rz * inv;
        float cm = 0.5f * (__cosf(d * (float)(M_PI / 10.0)) + 1.0f);
        sCm[e] = (d <= 10.0f) ? cm : 0.0f;
    }
    __syncthreads();

    // stage 1: A[e][k] = tf32(silu(Q[q][k] + P[gidx][k] + dist*wd[k] + b1[k]))
    #pragma unroll
    for (int it = 0; it < 8; ++it) {
        int idx = tid + it * 256;
        int e = idx >> 5;
        int k4 = (idx & 31) * 4;
        int q = bq4 + (e >> 4);
        float4 Qv = ldg4(g_Q + q * HDIM + k4);
        float4 Pv = ldg4(g_P + sGidx[e] * HDIM + k4);
        float4 wd = *(const float4*)(sWd + k4);
        float4 b1 = *(const float4*)(sB1 + k4);
        float dd = sDist[e];
        float4 r;
        r.x = tf32r(silu_f(Qv.x + Pv.x + dd * wd.x + b1.x));
        r.y = tf32r(silu_f(Qv.y + Pv.y + dd * wd.y + b1.y));
        r.z = tf32r(silu_f(Qv.z + Pv.z + dd * wd.z + b1.z));
        r.w = tf32r(silu_f(Qv.w + Pv.w + dd * wd.w + b1.w));
        *(float4*)(sT + e * 132 + k4) = r;
    }
    __syncthreads();

    // mma: warp grid 2(m) x 4(n); warp tile 32 rows x 32 cols
    const int mw = wid & 1;
    const int nw = wid >> 1;
    const int r4 = lane >> 2;
    const int kl = lane & 3;
    float c[2][4][4];
    #pragma unroll
    for (int s = 0; s < 2; ++s)
        #pragma unroll
        for (int ln = 0; ln < 4; ++ln)
            #pragma unroll
            for (int i = 0; i < 4; ++i) c[s][ln][i] = 0.0f;

    const float4* bfrag = (const float4*)(g_W2F + layer * 16384);
    float4 bq0 = __ldg(&bfrag[(nw * 2 + 0) * 32 + lane]);
    float4 bq1 = __ldg(&bfrag[(nw * 2 + 1) * 32 + lane]);
    #pragma unroll
    for (int k8 = 0; k8 < 16; ++k8) {
        float4 nb0, nb1;
        if (k8 < 15) {
            nb0 = __ldg(&bfrag[((k8 + 1) * 8 + nw * 2 + 0) * 32 + lane]);
            nb1 = __ldg(&bfrag[((k8 + 1) * 8 + nw * 2 + 1) * 32 + lane]);
        }
        int kc = k8 * 8 + kl;
        uint32_t a[2][4];
        #pragma unroll
        for (int s = 0; s < 2; ++s) {
            int rb = mw * 32 + s * 16 + r4;
            a[s][0] = __float_as_uint(sT[rb * 132 + kc]);
            a[s][1] = __float_as_uint(sT[(rb + 8) * 132 + kc]);
            a[s][2] = __float_as_uint(sT[rb * 132 + kc + 4]);
            a[s][3] = __float_as_uint(sT[(rb + 8) * 132 + kc + 4]);
        }
        #pragma unroll
        for (int s = 0; s < 2; ++s) {
            mma_tf32(c[s][0], a[s], __float_as_uint(bq0.x), __float_as_uint(bq0.y));
            mma_tf32(c[s][1], a[s], __float_as_uint(bq0.z), __float_as_uint(bq0.w));
            mma_tf32(c[s][2], a[s], __float_as_uint(bq1.x), __float_as_uint(bq1.y));
            mma_tf32(c[s][3], a[s], __float_as_uint(bq1.z), __float_as_uint(bq1.w));
        }
        bq0 = nb0; bq1 = nb1;
    }
    __syncthreads();   // all warps done reading sT (A)

    // epilogue: M[e][j] = silu(D + b2[j]) * Cm[e], into sT (reused as sM)
    #pragma unroll
    for (int s = 0; s < 2; ++s) {
        int r0 = mw * 32 + s * 16 + r4;
        int r1 = r0 + 8;
        float cm0 = sCm[r0], cm1 = sCm[r1];
        #pragma unroll
        for (int ln = 0; ln < 4; ++ln) {
            int c0 = nw * 32 + ln * 8 + 2 * kl;
            float bz0 = sB2[c0], bz1 = sB2[c0 + 1];
            *(float2*)(sT + r0 * 132 + c0) =
                make_float2(silu_f(c[s][ln][0] + bz0) * cm0, silu_f(c[s][ln][1] + bz1) * cm0);
            *(float2*)(sT + r1 * 132 + c0) =
                make_float2(silu_f(c[s][ln][2] + bz0) * cm1, silu_f(c[s][ln][3] + bz1) * cm1);
        }
    }
    __syncthreads();

    // m_aggr (layers 0..2)
    if (TOUT == 1) {
        #pragma unroll
        for (int it = 0; it < 2; ++it) {
            int idx = tid + it * 256;
            int q = idx >> 7;
            int j = idx & 127;
            float s = 0.0f;
            #pragma unroll
            for (int e = 0; e < DEG; ++e) s += sT[(q * DEG + e) * 132 + j];
            g_summ[(bq4 + q) * HDIM + j] = s * (1.0f / DEG);
        }
    }

    // coef: 64 edges, 4 threads/edge (interleaved cols -> conflict-free)
    {
        int e = tid >> 2, part = tid & 3;
        float acc[TOUT];
        #pragma unroll
        for (int t = 0; t < TOUT; ++t) acc[t] = 0.0f;
        const float* mr = sT + e * 132;
        #pragma unroll 8
        for (int i = 0; i < 32; ++i) {
            int j = i * 4 + part;
            float mv = mr[j];
            #pragma unroll
            for (int t = 0; t < TOUT; ++t) acc[t] = fmaf(mv, sFc[j * TOUT + t], acc[t]);
        }
        #pragma unroll
        for (int t = 0; t < TOUT; ++t) {
            float v = acc[t];
            v += __shfl_down_sync(0xFFFFFFFFu, v, 2);
            v += __shfl_down_sync(0xFFFFFFFFu, v, 1);
            if (part == 0) sCoef[e * TOUT + t] = v + __ldg(&coefB[t]);
        }
    }
    __syncthreads();

    // final reduction over 16 edges per query
    if (TOUT == 1) {
        if (tid < 12) {
            int q = tid / 3, d = tid % 3;
            const float* dirp = (d == 0) ? sDx : (d == 1) ? sDy : sDz;
            float s = 0.0f;
            #pragma unroll
            for (int e = 0; e < DEG; ++e) s += sCoef[q * DEG + e] * dirp[q * DEG + e];
            g_xq[(bq4 + q) * 3 + d] += s * (1.0f / DEG);
        }
    } else {
        if (tid < 4 * TOUT * 3) {
            int q = tid / (TOUT * 3);
            int r = tid % (TOUT * 3);
            int t = r / 3, d = r % 3;
            const float* dirp = (d == 0) ? sDx : (d == 1) ? sDy : sDz;
            float s = 0.0f;
            #pragma unroll
            for (int e = 0; e < DEG; ++e)
                s += sCoef[(q * DEG + e) * TOUT + t] * dirp[q * DEG + e];
            int gq = bq4 + q;
            out[(gq * TFIN + t) * 3 + d] =
                (g_xq[gq * 3 + d] - qpts[gq * 3 + d]) + s * (1.0f / DEG);
        }
    }
}

// -------- node kernel (fused): h-update + projection for next layer --------------
// dyn smem: sIn [64][260] floats = 66560B; sB1 128, sB2 128 floats
#define NODE_SMEM (66560 + 1024)

__global__ __launch_bounds__(256) void node_mma_kernel(
    const float* __restrict__ nb1_, const float* __restrict__ nb2_,
    int layer, int nextL)
{
    extern __shared__ float sm[];
    float* sIn = sm;                 // A1 [64][260]; later U/h_new [64][132]
    float* sB1 = sm + 16640;
    float* sB2 = sB1 + 128;

    const int tid = threadIdx.x;
    const int wid = tid >> 5;
    const int lane = tid & 31;
    const int base = blockIdx.x * 64;
    const bool isq = (base < NPTS);
    const float* hsrc = isq ? (g_hq + base * HDIM) : (g_hg + (base - NPTS) * HDIM);
    float* hdst = isq ? (g_hq + base * HDIM) : (g_hg + (base - NPTS) * HDIM);

    if (tid < 128) {
        sB1[tid] = nb1_[layer * HDIM + tid];
        sB2[tid] = nb2_[layer * HDIM + tid];
    }

    // A-stage: In[row][0:128]=h, [128:256]=m_aggr (0 for grid), tf32-rounded
    #pragma unroll
    for (int it = 0; it < 16; ++it) {
        int idx = tid + it * 256;          // float4 units, 4096 total
        int row = idx >> 6;
        int c4 = (idx & 63) * 4;
        float4 v;
        if (c4 < 128) {
            v = ldg4(hsrc + row * HDIM + c4);
        } else if (isq) {
            v = ldg4(g_summ + (base + row) * HDIM + (c4 - 128));
        } else {
            v = make_float4(0.f, 0.f, 0.f, 0.f);
        }
        v.x = tf32r(v.x); v.y = tf32r(v.y); v.z = tf32r(v.z); v.w = tf32r(v.w);
        *(float4*)(sIn + row * 260 + c4) = v;
    }
    __syncthreads();

    const int mw = wid & 1;
    const int nw = wid >> 1;
    const int r4 = lane >> 2;
    const int kl = lane & 3;

    float c[2][4][4];
    #pragma unroll
    for (int s = 0; s < 2; ++s)
        #pragma unroll
        for (int ln = 0; ln < 4; ++ln)
            #pragma unroll
            for (int i = 0; i < 4; ++i) c[s][ln][i] = 0.0f;

    // GEMM1: [64x256] @ W1 -> 64x128
    {
        const float4* bfrag = (const float4*)(g_W1F + layer * 32768);
        float4 bq0 = __ldg(&bfrag[(nw * 2 + 0) * 32 + lane]);
        float4 bq1 = __ldg(&bfrag[(nw * 2 + 1) * 32 + lane]);
        #pragma unroll
        for (int k8 = 0; k8 < 32; ++k8) {
            float4 nb0, nb1;
            if (k8 < 31) {
                nb0 = __ldg(&bfrag[((k8 + 1) * 8 + nw * 2 + 0) * 32 + lane]);
                nb1 = __ldg(&bfrag[((k8 + 1) * 8 + nw * 2 + 1) * 32 + lane]);
            }
            int kc = k8 * 8 + kl;
            uint32_t a[2][4];
            #pragma unroll
            for (int s = 0; s < 2; ++s) {
                int rb = mw * 32 + s * 16 + r4;
                a[s][0] = __float_as_uint(sIn[rb * 260 + kc]);
                a[s][1] = __float_as_uint(sIn[(rb + 8) * 260 + kc]);
                a[s][2] = __float_as_uint(sIn[rb * 260 + kc + 4]);
                a[s][3] = __float_as_uint(sIn[(rb + 8) * 260 + kc + 4]);
            }
            #pragma unroll
            for (int s = 0; s < 2; ++s) {
                mma_tf32(c[s][0], a[s], __float_as_uint(bq0.x), __float_as_uint(bq0.y));
                mma_tf32(c[s][1], a[s], __float_as_uint(bq0.z), __float_as_uint(bq0.w));
                mma_tf32(c[s][2], a[s], __float_as_uint(bq1.x), __float_as_uint(bq1.y));
                mma_tf32(c[s][3], a[s], __float_as_uint(bq1.z), __float_as_uint(bq1.w));
            }
            bq0 = nb0; bq1 = nb1;
        }
    }
    __syncthreads();   // all warps done reading sIn (A1)

    // U = tf32(silu(acc + b1)), into sIn reused as [64][132]
    #pragma unroll
    for (int s = 0; s < 2; ++s) {
        int r0 = mw * 32 + s * 16 + r4;
        int r1 = r0 + 8;
        #pragma unroll
        for (int ln = 0; ln < 4; ++ln) {
            int c0 = nw * 32 + ln * 8 + 2 * kl;
            float bz0 = sB1[c0], bz1 = sB1[c0 + 1];
            *(float2*)(sIn + r0 * 132 + c0) =
                make_float2(tf32r(silu_f(c[s][ln][0] + bz0)), tf32r(silu_f(c[s][ln][1] + bz1)));
            *(float2*)(sIn + r1 * 132 + c0) =
                make_float2(tf32r(silu_f(c[s][ln][2] + bz0)), tf32r(silu_f(c[s][ln][3] + bz1)));
        }
    }
    __syncthreads();

    // GEMM2: U[64x128] @ W2 -> 64x128
    #pragma unroll
    for (int s = 0; s < 2; ++s)
        #pragma unroll
        for (int ln = 0; ln < 4; ++ln)
            #pragma unroll
            for (int i = 0; i < 4; ++i) c[s][ln][i] = 0.0f;
    {
        const float4* bfrag = (const float4*)(g_WnF + layer * 16384);
        float4 bq0 = __ldg(&bfrag[(nw * 2 + 0) * 32 + lane]);
        float4 bq1 = __ldg(&bfrag[(nw * 2 + 1) * 32 + lane]);
        #pragma unroll
        for (int k8 = 0; k8 < 16; ++k8) {
            float4 nb0, nb1;
            if (k8 < 15) {
                nb0 = __ldg(&bfrag[((k8 + 1) * 8 + nw * 2 + 0) * 32 + lane]);
                nb1 = __ldg(&bfrag[((k8 + 1) * 8 + nw * 2 + 1) * 32 + lane]);
            }
            int kc = k8 * 8 + kl;
            uint32_t a[2][4];
            #pragma unroll
            for (int s = 0; s < 2; ++s) {
                int rb = mw * 32 + s * 16 + r4;
                a[s][0] = __float_as_uint(sIn[rb * 132 + kc]);
                a[s][1] = __float_as_uint(sIn[(rb + 8) * 132 + kc]);
                a[s][2] = __float_as_uint(sIn[rb * 132 + kc + 4]);
                a[s][3] = __float_as_uint(sIn[(rb + 8) * 132 + kc + 4]);
            }
            #pragma unroll
            for (int s = 0; s < 2; ++s) {
                mma_tf32(c[s][0], a[s], __float_as_uint(bq0.x), __float_as_uint(bq0.y));
                mma_tf32(c[s][1], a[s], __float_as_uint(bq0.z), __float_as_uint(bq0.w));
                mma_tf32(c[s][2], a[s], __float_as_uint(bq1.x), __float_as_uint(bq1.y));
                mma_tf32(c[s][3], a[s], __float_as_uint(bq1.z), __float_as_uint(bq1.w));
            }
            bq0 = nb0; bq1 = nb1;
        }
    }
    __syncthreads();   // all warps done reading sIn (U) before overwrite

    // h_new = hold + D + b2: write global AND stage tf32(h_new) into sIn [64][132]
    #pragma unroll
    for (int s = 0; s < 2; ++s) {
        int r0 = mw * 32 + s * 16 + r4;
        int r1 = r0 + 8;
        #pragma unroll
        for (int ln = 0; ln < 4; ++ln) {
            int c0 = nw * 32 + ln * 8 + 2 * kl;
            float bz0 = sB2[c0], bz1 = sB2[c0 + 1];
            float2 h0 = *(const float2*)(hdst + r0 * HDIM + c0);
            float2 h1 = *(const float2*)(hdst + r1 * HDIM + c0);
            float2 n0 = make_float2(h0.x + c[s][ln][0] + bz0, h0.y + c[s][ln][1] + bz1);
            float2 n1 = make_float2(h1.x + c[s][ln][2] + bz0, h1.y + c[s][ln][3] + bz1);
            *(float2*)(hdst + r0 * HDIM + c0) = n0;
            *(float2*)(hdst + r1 * HDIM + c0) = n1;
            *(float2*)(sIn + r0 * 132 + c0) = make_float2(tf32r(n0.x), tf32r(n0.y));
            *(float2*)(sIn + r1 * 132 + c0) = make_float2(tf32r(n1.x), tf32r(n1.y));
        }
    }
    __syncthreads();

    // GEMM3 (fused projection): P/Q[nextL] = h_new[64x128] @ We1half -> 64x128
    #pragma unroll
    for (int s = 0; s < 2; ++s)
        #pragma unroll
        for (int ln = 0; ln < 4; ++ln)
            #pragma unroll
            for (int i = 0; i < 4; ++i) c[s][ln][i] = 0.0f;
    {
        const float* wsrc = isq ? g_WqF : g_WgF;
        const float4* bfrag = (const float4*)(wsrc + nextL * 16384);
        float4 bq0 = __ldg(&bfrag[(nw * 2 + 0) * 32 + lane]);
        float4 bq1 = __ldg(&bfrag[(nw * 2 + 1) * 32 + lane]);
        #pragma unroll
        for (int k8 = 0; k8 < 16; ++k8) {
            float4 nb0, nb1;
            if (k8 < 15) {
                nb0 = __ldg(&bfrag[((k8 + 1) * 8 + nw * 2 + 0) * 32 + lane]);
                nb1 = __ldg(&bfrag[((k8 + 1) * 8 + nw * 2 + 1) * 32 + lane]);
            }
            int kc = k8 * 8 + kl;
            uint32_t a[2][4];
            #pragma unroll
            for (int s = 0; s < 2; ++s) {
                int rb = mw * 32 + s * 16 + r4;
                a[s][0] = __float_as_uint(sIn[rb * 132 + kc]);
                a[s][1] = __float_as_uint(sIn[(rb + 8) * 132 + kc]);
                a[s][2] = __float_as_uint(sIn[rb * 132 + kc + 4]);
                a[s][3] = __float_as_uint(sIn[(rb + 8) * 132 + kc + 4]);
            }
            #pragma unroll
            for (int s = 0; s < 2; ++s) {
                mma_tf32(c[s][0], a[s], __float_as_uint(bq0.x), __float_as_uint(bq0.y));
                mma_tf32(c[s][1], a[s], __float_as_uint(bq0.z), __float_as_uint(bq0.w));
                mma_tf32(c[s][2], a[s], __float_as_uint(bq1.x), __float_as_uint(bq1.y));
                mma_tf32(c[s][3], a[s], __float_as_uint(bq1.z), __float_as_uint(bq1.w));
            }
            bq0 = nb0; bq1 = nb1;
        }
    }

    // write projection (no bias)
    {
        float* outp = isq ? (g_Q + base * HDIM) : (g_P + (base - NPTS) * HDIM);
        #pragma unroll
        for (int s = 0; s < 2; ++s) {
            int r0 = mw * 32 + s * 16 + r4;
            int r1 = r0 + 8;
            #pragma unroll
            for (int ln = 0; ln < 4; ++ln) {
                int c0 = nw * 32 + ln * 8 + 2 * kl;
                *(float2*)(outp + r0 * HDIM + c0) = make_float2(c[s][ln][0], c[s][ln][1]);
                *(float2*)(outp + r1 * HDIM + c0) = make_float2(c[s][ln][2], c[s][ln][3]);
            }
        }
    }
}

// ---------------- launch ----------------
extern "C" void kernel_launch(void* const* d_in, const int* in_sizes, int n_in,
                              void* d_out, int out_size) {
    const float* qp    = (const float*)d_in[0];
    const float* codes = (const float*)d_in[1];
    const float* gpts  = (const float*)d_in[2];
    const float* eW1   = (const float*)d_in[3];
    const float* eb1   = (const float*)d_in[4];
    const float* eW2   = (const float*)d_in[5];
    const float* eb2   = (const float*)d_in[6];
    const float* cW    = (const float*)d_in[7];
    const float* cb    = (const float*)d_in[8];
    const float* fcW   = (const float*)d_in[9];
    const float* fcb   = (const float*)d_in[10];
    const float* nW1   = (const float*)d_in[11];
    const float* nb1   = (const float*)d_in[12];
    const float* nW2   = (const float*)d_in[13];
    const float* nb2   = (const float*)d_in[14];
    const int*   eidx  = (const int*)d_in[15];
    float* out = (float*)d_out;

    static bool attr_done = false;
    if (!attr_done) {
        cudaFuncSetAttribute(node_mma_kernel,
                             cudaFuncAttributeMaxDynamicSharedMemorySize, NODE_SMEM);
        attr_done = true;
    }

    init_kernel<<<(NPTS * HDIM + 255) / 256, 256>>>(qp, codes);

    float* w2f; cudaGetSymbolAddress((void**)&w2f, g_W2F);
    float* w1f; cudaGetSymbolAddress((void**)&w1f, g_W1F);
    float* wnf; cudaGetSymbolAddress((void**)&wnf, g_WnF);
    float* wqf; cudaGetSymbolAddress((void**)&wqf, g_WqF);
    float* wgf; cudaGetSymbolAddress((void**)&wgf, g_WgF);
    pack_kernel<<<(4 * 128 * 128 + 255) / 256, 256>>>(eW2, w2f, 128);
    pack_kernel<<<(4 * 256 * 128 + 255) / 256, 256>>>(nW1, w1f, 256);
    pack_kernel<<<(4 * 128 * 128 + 255) / 256, 256>>>(nW2, wnf, 128);
    pack_w1_kernel<<<(4 * 128 * 128 + 255) / 256, 256>>>(eW1, wqf, 128);
    pack_w1_kernel<<<(4 * 128 * 128 + 255) / 256, 256>>>(eW1, wgf, 0);

    // layer-0 projection: queries are zero (handled in init); grid = codes @ We1[0]
    proj_kernel<<<NGRID / 16, 128>>>(eW1);

    for (int L = 0; L < 4; ++L) {
        if (L < 3) {
            edge_mma_kernel<1><<<NPTS / 4, 256>>>(
                eidx, gpts, eW1, eb1, eb2, cW + L * HDIM, cb + L, qp, nullptr, L);
            node_mma_kernel<<<NNODES / 64, 256, NODE_SMEM>>>(nb1, nb2, L, L + 1);
        } else {
            edge_mma_kernel<TFIN><<<NPTS / 4, 256>>>(
                eidx, gpts, eW1, eb1, eb2, fcW, fcb, qp, out, L);
        }
    }
}

// round 16
// speedup vs baseline: 4.8434x; 1.1571x over previous
#include <cuda_runtime.h>
#include <cuda_fp16.h>
#include <math.h>
#include <stdint.h>

#define NPTS   16384
#define NGRID  4096
#define NNODES 20480
#define GPTS   512
#define HDIM   128
#define DEG    16
#define TFIN   5

// ---------------- scratch (device globals, no allocation) ----------------
__device__ float g_xq[NPTS * 3];
__device__ float g_hq[NPTS * HDIM];
__device__ float g_hg[NGRID * HDIM];
__device__ float g_P[NGRID * HDIM];
__device__ float g_Q[NPTS * HDIM];
__device__ float g_summ[NPTS * HDIM];
__device__ uint32_t g_W2H[4 * 8192];    // edge W2 fp16 fragments (K=128)
__device__ uint32_t g_W1H[4 * 16384];   // node W1 fp16 fragments (K=256)
__device__ uint32_t g_WnH[4 * 8192];    // node W2 fp16 fragments (K=128)
__device__ uint32_t g_WqH[4 * 8192];    // We1 query-half fp16 fragments
__device__ uint32_t g_WgH[4 * 8192];    // We1 grid-half  fp16 fragments

__device__ __forceinline__ float silu_f(float x) {
    return __fdividef(x, 1.0f + __expf(-x));
}
__device__ __forceinline__ float4 ldg4(const float* p) {
    return __ldg((const float4*)p);
}
__device__ __forceinline__ uint32_t f2h2(float a, float b) {
    __half2 h = __floats2half2_rn(a, b);
    return *(uint32_t*)&h;
}
__device__ __forceinline__ void mma_f16(float* c, const uint32_t* a,
                                        uint32_t b0, uint32_t b1) {
    asm volatile(
        "mma.sync.aligned.m16n8k16.row.col.f32.f16.f16.f32 "
        "{%0,%1,%2,%3}, {%4,%5,%6,%7}, {%8,%9}, {%0,%1,%2,%3};"
        : "+f"(c[0]), "+f"(c[1]), "+f"(c[2]), "+f"(c[3])
        : "r"(a[0]), "r"(a[1]), "r"(a[2]), "r"(a[3]), "r"(b0), "r"(b1));
}

// ---- 4x4 scalar tile helpers (proj0 kernel) ----
#define FMA_TILE(acc, a, b) do {                                             \
    acc[0].x = fmaf(a.x, b.x, acc[0].x); acc[0].y = fmaf(a.x, b.y, acc[0].y);\
    acc[0].z = fmaf(a.x, b.z, acc[0].z); acc[0].w = fmaf(a.x, b.w, acc[0].w);\
    acc[1].x = fmaf(a.y, b.x, acc[1].x); acc[1].y = fmaf(a.y, b.y, acc[1].y);\
    acc[1].z = fmaf(a.y, b.z, acc[1].z); acc[1].w = fmaf(a.y, b.w, acc[1].w);\
    acc[2].x = fmaf(a.z, b.x, acc[2].x); acc[2].y = fmaf(a.z, b.y, acc[2].y);\
    acc[2].z = fmaf(a.z, b.z, acc[2].z); acc[2].w = fmaf(a.z, b.w, acc[2].w);\
    acc[3].x = fmaf(a.w, b.x, acc[3].x); acc[3].y = fmaf(a.w, b.y, acc[3].y);\
    acc[3].z = fmaf(a.w, b.z, acc[3].z); acc[3].w = fmaf(a.w, b.w, acc[3].w);\
} while (0)
#define ZERO4(acc) do {                                                      \
    acc[0] = make_float4(0.f,0.f,0.f,0.f); acc[1] = make_float4(0.f,0.f,0.f,0.f); \
    acc[2] = make_float4(0.f,0.f,0.f,0.f); acc[3] = make_float4(0.f,0.f,0.f,0.f); \
} while (0)

// ---------------- init ----------------
__global__ void init_kernel(const float* __restrict__ qp, const float* __restrict__ codes) {
    int i = blockIdx.x * blockDim.x + threadIdx.x;
    if (i < NPTS * HDIM)  { g_hq[i] = 0.0f; g_Q[i] = 0.0f; }  // Q0 = 0@W = 0
    if (i < NGRID * HDIM) g_hg[i] = codes[i];
    if (i < NPTS * 3)     g_xq[i] = qp[i];
}

// ---------- fp16 B fragment packer (N=128, contiguous src [4][K][128]) ----------
// u32 m (per layer): j=m&3, lane=(m>>2)&31, slot=m>>7; s8=slot&7, k16=slot>>3
//   nt = s8*2 + (j>>1); n = nt*8 + (lane>>2); k = k16*16 + (lane&3)*2 + (j&1)*8
//   value = half2(src[k][n], src[k+1][n])
__global__ void packh_kernel(const float* __restrict__ src, uint32_t* __restrict__ dst,
                             int K) {
    int m = blockIdx.x * blockDim.x + threadIdx.x;
    int perL = K * 64;
    if (m >= 4 * perL) return;
    int layer = m / perL;
    int rem = m % perL;
    int j = rem & 3;
    int lane = (rem >> 2) & 31;
    int slot = rem >> 7;
    int s8 = slot & 7;
    int k16 = slot >> 3;
    int nt = s8 * 2 + (j >> 1);
    int n = nt * 8 + (lane >> 2);
    int k = k16 * 16 + (lane & 3) * 2 + ((j & 1) << 3);
    const float* S = src + (size_t)layer * K * 128;
    dst[m] = f2h2(S[k * 128 + n], S[(k + 1) * 128 + n]);
}

// ---- We1 sub-matrix fp16 packer: src [4][257][128], rows row_off..row_off+127 ----
__global__ void packh_w1_kernel(const float* __restrict__ src, uint32_t* __restrict__ dst,
                                int row_off) {
    int m = blockIdx.x * blockDim.x + threadIdx.x;
    if (m >= 4 * 8192) return;
    int layer = m >> 13;
    int rem = m & 8191;
    int j = rem & 3;
    int lane = (rem >> 2) & 31;
    int slot = rem >> 7;
    int s8 = slot & 7;
    int k16 = slot >> 3;
    int nt = s8 * 2 + (j >> 1);
    int n = nt * 8 + (lane >> 2);
    int k = k16 * 16 + (lane & 3) * 2 + ((j & 1) << 3);
    const float* S = src + (size_t)layer * 257 * 128 + (size_t)row_off * 128;
    dst[m] = f2h2(S[k * 128 + n], S[(k + 1) * 128 + n]);
}

// ---------------- proj0: grid nodes only, layer 0 (scalar, fp32) ----------------
#define PK 20
__global__ __launch_bounds__(128) void proj_kernel(const float* __restrict__ eW1) {
    __shared__ float sAp[HDIM * PK];
    const int tid = threadIdx.x;
    const int j4 = (tid & 31) * 4;
    const int mq = tid >> 5;
    const int gbase = blockIdx.x * 16;
    const float* W = eW1;    // layer 0, rows 0:128 (grid half)

    #pragma unroll
    for (int n = 0; n < 16; ++n)
        sAp[tid * PK + n] = g_hg[(gbase + n) * HDIM + tid];
    __syncthreads();

    float4 acc[4]; ZERO4(acc);
    #pragma unroll 4
    for (int k = 0; k < HDIM; ++k) {
        float4 a = *(const float4*)(sAp + k * PK + mq * 4);
        float4 b = ldg4(W + k * HDIM + j4);
        FMA_TILE(acc, a, b);
    }
    #pragma unroll
    for (int mi = 0; mi < 4; ++mi)
        *(float4*)(g_P + (gbase + mq * 4 + mi) * HDIM + j4) = acc[mi];
}

// ---------------- edge kernel: fp16 mma, 64 edges (4 queries) per block ----------
// dyn smem: sA half [64][136] = 17408; sM float [64][132] = 33792; misc
#define OFF_M     17408
#define OFF_GIDX  51200
#define OFF_DIST  51456
#define OFF_DX    51712
#define OFF_DY    51968
#define OFF_DZ    52224
#define OFF_CM    52480
#define OFF_B2    52736
#define OFF_B1    53248
#define OFF_WD    53760
#define OFF_FC    54272
#define OFF_COEF  56832
#define EDGE_SMEM 58368

template <int TOUT>
__global__ __launch_bounds__(256) void edge_mma_kernel(
    const int*   __restrict__ erow,
    const float* __restrict__ gpts,
    const float* __restrict__ eW1, const float* __restrict__ eb1,
    const float* __restrict__ eb2,
    const float* __restrict__ coefW, const float* __restrict__ coefB,
    const float* __restrict__ qpts, float* __restrict__ out, int layer)
{
    extern __shared__ char sb[];
    __half* sA   = (__half*)sb;                  // [64][136]
    float* sM    = (float*)(sb + OFF_M);         // [64][132]
    int*   sGidx = (int*)  (sb + OFF_GIDX);
    float* sDist = (float*)(sb + OFF_DIST);
    float* sDx   = (float*)(sb + OFF_DX);
    float* sDy   = (float*)(sb + OFF_DY);
    float* sDz   = (float*)(sb + OFF_DZ);
    float* sCm   = (float*)(sb + OFF_CM);
    float* sB2   = (float*)(sb + OFF_B2);
    float* sB1   = (float*)(sb + OFF_B1);
    float* sWd   = (float*)(sb + OFF_WD);
    float* sFc   = (float*)(sb + OFF_FC);
    float* sCoef = (float*)(sb + OFF_COEF);

    const int tid = threadIdx.x;
    const int wid = tid >> 5;
    const int lane = tid & 31;
    const int bq4 = blockIdx.x * 4;
    const float* W1L = eW1 + (size_t)layer * 257 * HDIM;

    if (tid < 128) {
        sB2[tid] = eb2[layer * HDIM + tid];
        sB1[tid] = eb1[layer * HDIM + tid];
        sWd[tid] = W1L[256 * HDIM + tid];
        #pragma unroll
        for (int t = 0; t < TOUT; ++t) sFc[tid * TOUT + t] = coefW[tid * TOUT + t];
    }
    if (tid < 64) {
        int e = tid;
        int q = bq4 + (e >> 4);
        int rv = erow[q * DEG + (e & 15)];
        int gidx = rv - NPTS;
        int gl = gidx & (GPTS - 1);
        float rx = gpts[gl * 3 + 0] - g_xq[q * 3 + 0];
        float ry = gpts[gl * 3 + 1] - g_xq[q * 3 + 1];
        float rz = gpts[gl * 3 + 2] - g_xq[q * 3 + 2];
        float d = sqrtf(rx * rx + ry * ry + rz * rz);
        float inv = 1.0f / (d + 1e-8f);
        sGidx[e] = gidx; sDist[e] = d;
        sDx[e] = rx * inv; sDy[e] = ry * inv; sDz[e] = rz * inv;
        float cm = 0.5f * (__cosf(d * (float)(M_PI / 10.0)) + 1.0f);
        sCm[e] = (d <= 10.0f) ? cm : 0.0f;
    }
    __syncthreads();

    // stage 1: A[e][k] = f16(silu(Q[q][k] + P[gidx][k] + dist*wd[k] + b1[k]))
    #pragma unroll
    for (int it = 0; it < 8; ++it) {
        int idx = tid + it * 256;
        int e = idx >> 5;
        int k4 = (idx & 31) * 4;
        int q = bq4 + (e >> 4);
        float4 Qv = ldg4(g_Q + q * HDIM + k4);
        float4 Pv = ldg4(g_P + sGidx[e] * HDIM + k4);
        float4 wd = *(const float4*)(sWd + k4);
        float4 b1 = *(const float4*)(sB1 + k4);
        float dd = sDist[e];
        uint2 hv;
        hv.x = f2h2(silu_f(Qv.x + Pv.x + dd * wd.x + b1.x),
                    silu_f(Qv.y + Pv.y + dd * wd.y + b1.y));
        hv.y = f2h2(silu_f(Qv.z + Pv.z + dd * wd.z + b1.z),
                    silu_f(Qv.w + Pv.w + dd * wd.w + b1.w));
        *(uint2*)(sA + e * 136 + k4) = hv;
    }
    __syncthreads();

    // mma: warp grid 2(m) x 4(n); warp tile 32 rows x 32 cols; k16 steps
    const int mw = wid & 1;
    const int nw = wid >> 1;
    const int r4 = lane >> 2;
    const int kl = lane & 3;
    float c[2][4][4];
    #pragma unroll
    for (int s = 0; s < 2; ++s)
        #pragma unroll
        for (int ln = 0; ln < 4; ++ln)
            #pragma unroll
            for (int i = 0; i < 4; ++i) c[s][ln][i] = 0.0f;

    {
        const uint4* bfrag = (const uint4*)(g_W2H + layer * 8192);
        uint4 bq0 = __ldg(&bfrag[(nw * 2 + 0) * 32 + lane]);
        uint4 bq1 = __ldg(&bfrag[(nw * 2 + 1) * 32 + lane]);
        #pragma unroll
        for (int k16 = 0; k16 < 8; ++k16) {
            uint4 nb0, nb1;
            if (k16 < 7) {
                nb0 = __ldg(&bfrag[((k16 + 1) * 8 + nw * 2 + 0) * 32 + lane]);
                nb1 = __ldg(&bfrag[((k16 + 1) * 8 + nw * 2 + 1) * 32 + lane]);
            }
            int kb = k16 * 16 + kl * 2;
            uint32_t a[2][4];
            #pragma unroll
            for (int s = 0; s < 2; ++s) {
                int rb = mw * 32 + s * 16 + r4;
                a[s][0] = *(const uint32_t*)(sA + rb * 136 + kb);
                a[s][1] = *(const uint32_t*)(sA + (rb + 8) * 136 + kb);
                a[s][2] = *(const uint32_t*)(sA + rb * 136 + kb + 8);
                a[s][3] = *(const uint32_t*)(sA + (rb + 8) * 136 + kb + 8);
            }
            #pragma unroll
            for (int s = 0; s < 2; ++s) {
                mma_f16(c[s][0], a[s], bq0.x, bq0.y);
                mma_f16(c[s][1], a[s], bq0.z, bq0.w);
                mma_f16(c[s][2], a[s], bq1.x, bq1.y);
                mma_f16(c[s][3], a[s], bq1.z, bq1.w);
            }
            bq0 = nb0; bq1 = nb1;
        }
    }
    __syncthreads();

    // epilogue: M[e][j] = silu(D + b2[j]) * Cm[e], fp32 into sM
    #pragma unroll
    for (int s = 0; s < 2; ++s) {
        int r0 = mw * 32 + s * 16 + r4;
        int r1 = r0 + 8;
        float cm0 = sCm[r0], cm1 = sCm[r1];
        #pragma unroll
        for (int ln = 0; ln < 4; ++ln) {
            int c0 = nw * 32 + ln * 8 + 2 * kl;
            float bz0 = sB2[c0], bz1 = sB2[c0 + 1];
            *(float2*)(sM + r0 * 132 + c0) =
                make_float2(silu_f(c[s][ln][0] + bz0) * cm0, silu_f(c[s][ln][1] + bz1) * cm0);
            *(float2*)(sM + r1 * 132 + c0) =
                make_float2(silu_f(c[s][ln][2] + bz0) * cm1, silu_f(c[s][ln][3] + bz1) * cm1);
        }
    }
    __syncthreads();

    // m_aggr (layers 0..2)
    if (TOUT == 1) {
        #pragma unroll
        for (int it = 0; it < 2; ++it) {
            int idx = tid + it * 256;
            int q = idx >> 7;
            int j = idx & 127;
            float s = 0.0f;
            #pragma unroll
            for (int e = 0; e < DEG; ++e) s += sM[(q * DEG + e) * 132 + j];
            g_summ[(bq4 + q) * HDIM + j] = s * (1.0f / DEG);
        }
    }

    // coef: 64 edges, 4 threads/edge (interleaved cols -> conflict-free)
    {
        int e = tid >> 2, part = tid & 3;
        float acc[TOUT];
        #pragma unroll
        for (int t = 0; t < TOUT; ++t) acc[t] = 0.0f;
        const float* mr = sM + e * 132;
        #pragma unroll 8
        for (int i = 0; i < 32; ++i) {
            int j = i * 4 + part;
            float mv = mr[j];
            #pragma unroll
            for (int t = 0; t < TOUT; ++t) acc[t] = fmaf(mv, sFc[j * TOUT + t], acc[t]);
        }
        #pragma unroll
        for (int t = 0; t < TOUT; ++t) {
            float v = acc[t];
            v += __shfl_down_sync(0xFFFFFFFFu, v, 2);
            v += __shfl_down_sync(0xFFFFFFFFu, v, 1);
            if (part == 0) sCoef[e * TOUT + t] = v + __ldg(&coefB[t]);
        }
    }
    __syncthreads();

    // final reduction over 16 edges per query
    if (TOUT == 1) {
        if (tid < 12) {
            int q = tid / 3, d = tid % 3;
            const float* dirp = (d == 0) ? sDx : (d == 1) ? sDy : sDz;
            float s = 0.0f;
            #pragma unroll
            for (int e = 0; e < DEG; ++e) s += sCoef[q * DEG + e] * dirp[q * DEG + e];
            g_xq[(bq4 + q) * 3 + d] += s * (1.0f / DEG);
        }
    } else {
        if (tid < 4 * TOUT * 3) {
            int q = tid / (TOUT * 3);
            int r = tid % (TOUT * 3);
            int t = r / 3, d = r % 3;
            const float* dirp = (d == 0) ? sDx : (d == 1) ? sDy : sDz;
            float s = 0.0f;
            #pragma unroll
            for (int e = 0; e < DEG; ++e)
                s += sCoef[(q * DEG + e) * TOUT + t] * dirp[q * DEG + e];
            int gq = bq4 + q;
            out[(gq * TFIN + t) * 3 + d] =
                (g_xq[gq * 3 + d] - qpts[gq * 3 + d]) + s * (1.0f / DEG);
        }
    }
}

// -------- node kernel (fused): h-update + projection for next layer, fp16 mma ----
__global__ __launch_bounds__(256) void node_mma_kernel(
    const float* __restrict__ nb1_, const float* __restrict__ nb2_,
    int layer, int nextL)
{
    __shared__ __align__(16) __half sIn[64 * 264];  // A1 [64][264]; later [64][136]
    __shared__ float sB1[128], sB2[128];

    const int tid = threadIdx.x;
    const int wid = tid >> 5;
    const int lane = tid & 31;
    const int base = blockIdx.x * 64;
    const bool isq = (base < NPTS);
    const float* hsrc = isq ? (g_hq + base * HDIM) : (g_hg + (base - NPTS) * HDIM);
    float* hdst = isq ? (g_hq + base * HDIM) : (g_hg + (base - NPTS) * HDIM);

    if (tid < 128) {
        sB1[tid] = nb1_[layer * HDIM + tid];
        sB2[tid] = nb2_[layer * HDIM + tid];
    }

    // A-stage: In[row][0:128]=h, [128:256]=m_aggr (0 for grid), fp16
    #pragma unroll
    for (int it = 0; it < 16; ++it) {
        int idx = tid + it * 256;
        int row = idx >> 6;
        int c4 = (idx & 63) * 4;
        float4 v;
        if (c4 < 128) {
            v = ldg4(hsrc + row * HDIM + c4);
        } else if (isq) {
            v = ldg4(g_summ + (base + row) * HDIM + (c4 - 128));
        } else {
            v = make_float4(0.f, 0.f, 0.f, 0.f);
        }
        uint2 hv;
        hv.x = f2h2(v.x, v.y);
        hv.y = f2h2(v.z, v.w);
        *(uint2*)(sIn + row * 264 + c4) = hv;
    }
    __syncthreads();

    const int mw = wid & 1;
    const int nw = wid >> 1;
    const int r4 = lane >> 2;
    const int kl = lane & 3;

    float c[2][4][4];
    #pragma unroll
    for (int s = 0; s < 2; ++s)
        #pragma unroll
        for (int ln = 0; ln < 4; ++ln)
            #pragma unroll
            for (int i = 0; i < 4; ++i) c[s][ln][i] = 0.0f;

    // GEMM1: [64x256] @ W1 -> 64x128
    {
        const uint4* bfrag = (const uint4*)(g_W1H + layer * 16384);
        uint4 bq0 = __ldg(&bfrag[(nw * 2 + 0) * 32 + lane]);
        uint4 bq1 = __ldg(&bfrag[(nw * 2 + 1) * 32 + lane]);
        #pragma unroll
        for (int k16 = 0; k16 < 16; ++k16) {
            uint4 nb0, nb1;
            if (k16 < 15) {
                nb0 = __ldg(&bfrag[((k16 + 1) * 8 + nw * 2 + 0) * 32 + lane]);
                nb1 = __ldg(&bfrag[((k16 + 1) * 8 + nw * 2 + 1) * 32 + lane]);
            }
            int kb = k16 * 16 + kl * 2;
            uint32_t a[2][4];
            #pragma unroll
            for (int s = 0; s < 2; ++s) {
                int rb = mw * 32 + s * 16 + r4;
                a[s][0] = *(const uint32_t*)(sIn + rb * 264 + kb);
                a[s][1] = *(const uint32_t*)(sIn + (rb + 8) * 264 + kb);
                a[s][2] = *(const uint32_t*)(sIn + rb * 264 + kb + 8);
                a[s][3] = *(const uint32_t*)(sIn + (rb + 8) * 264 + kb + 8);
            }
            #pragma unroll
            for (int s = 0; s < 2; ++s) {
                mma_f16(c[s][0], a[s], bq0.x, bq0.y);
                mma_f16(c[s][1], a[s], bq0.z, bq0.w);
                mma_f16(c[s][2], a[s], bq1.x, bq1.y);
                mma_f16(c[s][3], a[s], bq1.z, bq1.w);
            }
            bq0 = nb0; bq1 = nb1;
        }
    }
    __syncthreads();   // all warps done reading sIn (A1)

    // U = f16(silu(acc + b1)), into sIn reused as [64][136]
    #pragma unroll
    for (int s = 0; s < 2; ++s) {
        int r0 = mw * 32 + s * 16 + r4;
        int r1 = r0 + 8;
        #pragma unroll
        for (int ln = 0; ln < 4; ++ln) {
            int c0 = nw * 32 + ln * 8 + 2 * kl;
            float bz0 = sB1[c0], bz1 = sB1[c0 + 1];
            *(uint32_t*)(sIn + r0 * 136 + c0) =
                f2h2(silu_f(c[s][ln][0] + bz0), silu_f(c[s][ln][1] + bz1));
            *(uint32_t*)(sIn + r1 * 136 + c0) =
                f2h2(silu_f(c[s][ln][2] + bz0), silu_f(c[s][ln][3] + bz1));
        }
    }
    __syncthreads();

    // GEMM2: U[64x128] @ W2 -> 64x128
    #pragma unroll
    for (int s = 0; s < 2; ++s)
        #pragma unroll
        for (int ln = 0; ln < 4; ++ln)
            #pragma unroll
            for (int i = 0; i < 4; ++i) c[s][ln][i] = 0.0f;
    {
        const uint4* bfrag = (const uint4*)(g_WnH + layer * 8192);
        uint4 bq0 = __ldg(&bfrag[(nw * 2 + 0) * 32 + lane]);
        uint4 bq1 = __ldg(&bfrag[(nw * 2 + 1) * 32 + lane]);
        #pragma unroll
        for (int k16 = 0; k16 < 8; ++k16) {
            uint4 nb0, nb1;
            if (k16 < 7) {
                nb0 = __ldg(&bfrag[((k16 + 1) * 8 + nw * 2 + 0) * 32 + lane]);
                nb1 = __ldg(&bfrag[((k16 + 1) * 8 + nw * 2 + 1) * 32 + lane]);
            }
            int kb = k16 * 16 + kl * 2;
            uint32_t a[2][4];
            #pragma unroll
            for (int s = 0; s < 2; ++s) {
                int rb = mw * 32 + s * 16 + r4;
                a[s][0] = *(const uint32_t*)(sIn + rb * 136 + kb);
                a[s][1] = *(const uint32_t*)(sIn + (rb + 8) * 136 + kb);
                a[s][2] = *(const uint32_t*)(sIn + rb * 136 + kb + 8);
                a[s][3] = *(const uint32_t*)(sIn + (rb + 8) * 136 + kb + 8);
            }
            #pragma unroll
            for (int s = 0; s < 2; ++s) {
                mma_f16(c[s][0], a[s], bq0.x, bq0.y);
                mma_f16(c[s][1], a[s], bq0.z, bq0.w);
                mma_f16(c[s][2], a[s], bq1.x, bq1.y);
                mma_f16(c[s][3], a[s], bq1.z, bq1.w);
            }
            bq0 = nb0; bq1 = nb1;
        }
    }
    __syncthreads();   // all warps done reading sIn (U) before overwrite

    // h_new = hold + D + b2: write global AND stage f16(h_new) into sIn [64][136]
    #pragma unroll
    for (int s = 0; s < 2; ++s) {
        int r0 = mw * 32 + s * 16 + r4;
        int r1 = r0 + 8;
        #pragma unroll
        for (int ln = 0; ln < 4; ++ln) {
            int c0 = nw * 32 + ln * 8 + 2 * kl;
            float bz0 = sB2[c0], bz1 = sB2[c0 + 1];
            float2 h0 = *(const float2*)(hdst + r0 * HDIM + c0);
            float2 h1 = *(const float2*)(hdst + r1 * HDIM + c0);
            float2 n0 = make_float2(h0.x + c[s][ln][0] + bz0, h0.y + c[s][ln][1] + bz1);
            float2 n1 = make_float2(h1.x + c[s][ln][2] + bz0, h1.y + c[s][ln][3] + bz1);
            *(float2*)(hdst + r0 * HDIM + c0) = n0;
            *(float2*)(hdst + r1 * HDIM + c0) = n1;
            *(uint32_t*)(sIn + r0 * 136 + c0) = f2h2(n0.x, n0.y);
            *(uint32_t*)(sIn + r1 * 136 + c0) = f2h2(n1.x, n1.y);
        }
    }
    __syncthreads();

    // GEMM3 (fused projection): P/Q[nextL] = h_new[64x128] @ We1half -> 64x128
    #pragma unroll
    for (int s = 0; s < 2; ++s)
        #pragma unroll
        for (int ln = 0; ln < 4; ++ln)
            #pragma unroll
            for (int i = 0; i < 4; ++i) c[s][ln][i] = 0.0f;
    {
        const uint32_t* wsrc = isq ? g_WqH : g_WgH;
        const uint4* bfrag = (const uint4*)(wsrc + nextL * 8192);
        uint4 bq0 = __ldg(&bfrag[(nw * 2 + 0) * 32 + lane]);
        uint4 bq1 = __ldg(&bfrag[(nw * 2 + 1) * 32 + lane]);
        #pragma unroll
        for (int k16 = 0; k16 < 8; ++k16) {
            uint4 nb0, nb1;
            if (k16 < 7) {
                nb0 = __ldg(&bfrag[((k16 + 1) * 8 + nw * 2 + 0) * 32 + lane]);
                nb1 = __ldg(&bfrag[((k16 + 1) * 8 + nw * 2 + 1) * 32 + lane]);
            }
            int kb = k16 * 16 + kl * 2;
            uint32_t a[2][4];
            #pragma unroll
            for (int s = 0; s < 2; ++s) {
                int rb = mw * 32 + s * 16 + r4;
                a[s][0] = *(const uint32_t*)(sIn + rb * 136 + kb);
                a[s][1] = *(const uint32_t*)(sIn + (rb + 8) * 136 + kb);
                a[s][2] = *(const uint32_t*)(sIn + rb * 136 + kb + 8);
                a[s][3] = *(const uint32_t*)(sIn + (rb + 8) * 136 + kb + 8);
            }
            #pragma unroll
            for (int s = 0; s < 2; ++s) {
                mma_f16(c[s][0], a[s], bq0.x, bq0.y);
                mma_f16(c[s][1], a[s], bq0.z, bq0.w);
                mma_f16(c[s][2], a[s], bq1.x, bq1.y);
                mma_f16(c[s][3], a[s], bq1.z, bq1.w);
            }
            bq0 = nb0; bq1 = nb1;
        }
    }

    // write projection (no bias)
    {
        float* outp = isq ? (g_Q + base * HDIM) : (g_P + (base - NPTS) * HDIM);
        #pragma unroll
        for (int s = 0; s < 2; ++s) {
            int r0 = mw * 32 + s * 16 + r4;
            int r1 = r0 + 8;
            #pragma unroll
            for (int ln = 0; ln < 4; ++ln) {
                int c0 = nw * 32 + ln * 8 + 2 * kl;
                *(float2*)(outp + r0 * HDIM + c0) = make_float2(c[s][ln][0], c[s][ln][1]);
                *(float2*)(outp + r1 * HDIM + c0) = make_float2(c[s][ln][2], c[s][ln][3]);
            }
        }
    }
}

// ---------------- launch ----------------
extern "C" void kernel_launch(void* const* d_in, const int* in_sizes, int n_in,
                              void* d_out, int out_size) {
    const float* qp    = (const float*)d_in[0];
    const float* codes = (const float*)d_in[1];
    const float* gpts  = (const float*)d_in[2];
    const float* eW1   = (const float*)d_in[3];
    const float* eb1   = (const float*)d_in[4];
    const float* eW2   = (const float*)d_in[5];
    const float* eb2   = (const float*)d_in[6];
    const float* cW    = (const float*)d_in[7];
    const float* cb    = (const float*)d_in[8];
    const float* fcW   = (const float*)d_in[9];
    const float* fcb   = (const float*)d_in[10];
    const float* nW1   = (const float*)d_in[11];
    const float* nb1   = (const float*)d_in[12];
    const float* nW2   = (const float*)d_in[13];
    const float* nb2   = (const float*)d_in[14];
    const int*   eidx  = (const int*)d_in[15];
    float* out = (float*)d_out;

    static bool attr_done = false;
    if (!attr_done) {
        cudaFuncSetAttribute(edge_mma_kernel<1>,
                             cudaFuncAttributeMaxDynamicSharedMemorySize, EDGE_SMEM);
        cudaFuncSetAttribute(edge_mma_kernel<TFIN>,
                             cudaFuncAttributeMaxDynamicSharedMemorySize, EDGE_SMEM);
        attr_done = true;
    }

    init_kernel<<<(NPTS * HDIM + 255) / 256, 256>>>(qp, codes);

    uint32_t* w2h; cudaGetSymbolAddress((void**)&w2h, g_W2H);
    uint32_t* w1h; cudaGetSymbolAddress((void**)&w1h, g_W1H);
    uint32_t* wnh; cudaGetSymbolAddress((void**)&wnh, g_WnH);
    uint32_t* wqh; cudaGetSymbolAddress((void**)&wqh, g_WqH);
    uint32_t* wgh; cudaGetSymbolAddress((void**)&wgh, g_WgH);
    packh_kernel<<<(4 * 8192 + 255) / 256, 256>>>(eW2, w2h, 128);
    packh_kernel<<<(4 * 16384 + 255) / 256, 256>>>(nW1, w1h, 256);
    packh_kernel<<<(4 * 8192 + 255) / 256, 256>>>(nW2, wnh, 128);
    packh_w1_kernel<<<(4 * 8192 + 255) / 256, 256>>>(eW1, wqh, 128);
    packh_w1_kernel<<<(4 * 8192 + 255) / 256, 256>>>(eW1, wgh, 0);

    // layer-0 projection: queries are zero (handled in init); grid = codes @ We1[0]
    proj_kernel<<<NGRID / 16, 128>>>(eW1);

    for (int L = 0; L < 4; ++L) {
        if (L < 3) {
            edge_mma_kernel<1><<<NPTS / 4, 256, EDGE_SMEM>>>(
                eidx, gpts, eW1, eb1, eb2, cW + L * HDIM, cb + L, qp, nullptr, L);
            node_mma_kernel<<<NNODES / 64, 256>>>(nb1, nb2, L, L + 1);
        } else {
            edge_mma_kernel<TFIN><<<NPTS / 4, 256, EDGE_SMEM>>>(
                eidx, gpts, eW1, eb1, eb2, fcW, fcb, qp, out, L);
        }
    }
}

// round 17
// speedup vs baseline: 5.1920x; 1.0720x over previous
#include <cuda_runtime.h>
#include <cuda_fp16.h>
#include <math.h>
#include <stdint.h>

#define NPTS   16384
#define NGRID  4096
#define NNODES 20480
#define GPTS   512
#define HDIM   128
#define DEG    16
#define TFIN   5

// ---------------- scratch (device globals, no allocation) ----------------
__device__ float g_xq[NPTS * 3];
__device__ float g_hq[NPTS * HDIM];
__device__ float g_hg[NGRID * HDIM];
__device__ float g_P[NGRID * HDIM];
__device__ float g_Q[NPTS * HDIM];
__device__ float g_summ[NPTS * HDIM];
__device__ uint32_t g_W2H[4 * 8192];    // edge W2 fp16 fragments (K=128)
__device__ uint32_t g_W1H[4 * 16384];   // node W1 fp16 fragments (K=256)
__device__ uint32_t g_WnH[4 * 8192];    // node W2 fp16 fragments (K=128)
__device__ uint32_t g_WqH[4 * 8192];    // We1 query-half fp16 fragments
__device__ uint32_t g_WgH[4 * 8192];    // We1 grid-half  fp16 fragments

// silu via MUFU.TANH: x*sigmoid(x) = 0.5x(1+tanh(x/2)) — 1 MUFU instead of 2
__device__ __forceinline__ float silu_f(float x) {
    float t;
    asm("tanh.approx.f32 %0, %1;" : "=f"(t) : "f"(0.5f * x));
    return 0.5f * x * (1.0f + t);
}
__device__ __forceinline__ float4 ldg4(const float* p) {
    return __ldg((const float4*)p);
}
__device__ __forceinline__ uint32_t f2h2(float a, float b) {
    __half2 h = __floats2half2_rn(a, b);
    return *(uint32_t*)&h;
}
__device__ __forceinline__ void mma_f16(float* c, const uint32_t* a,
                                        uint32_t b0, uint32_t b1) {
    asm volatile(
        "mma.sync.aligned.m16n8k16.row.col.f32.f16.f16.f32 "
        "{%0,%1,%2,%3}, {%4,%5,%6,%7}, {%8,%9}, {%0,%1,%2,%3};"
        : "+f"(c[0]), "+f"(c[1]), "+f"(c[2]), "+f"(c[3])
        : "r"(a[0]), "r"(a[1]), "r"(a[2]), "r"(a[3]), "r"(b0), "r"(b1));
}

// ---- 4x4 scalar tile helpers (proj0 kernel) ----
#define FMA_TILE(acc, a, b) do {                                             \
    acc[0].x = fmaf(a.x, b.x, acc[0].x); acc[0].y = fmaf(a.x, b.y, acc[0].y);\
    acc[0].z = fmaf(a.x, b.z, acc[0].z); acc[0].w = fmaf(a.x, b.w, acc[0].w);\
    acc[1].x = fmaf(a.y, b.x, acc[1].x); acc[1].y = fmaf(a.y, b.y, acc[1].y);\
    acc[1].z = fmaf(a.y, b.z, acc[1].z); acc[1].w = fmaf(a.y, b.w, acc[1].w);\
    acc[2].x = fmaf(a.z, b.x, acc[2].x); acc[2].y = fmaf(a.z, b.y, acc[2].y);\
    acc[2].z = fmaf(a.z, b.z, acc[2].z); acc[2].w = fmaf(a.z, b.w, acc[2].w);\
    acc[3].x = fmaf(a.w, b.x, acc[3].x); acc[3].y = fmaf(a.w, b.y, acc[3].y);\
    acc[3].z = fmaf(a.w, b.z, acc[3].z); acc[3].w = fmaf(a.w, b.w, acc[3].w);\
} while (0)
#define ZERO4(acc) do {                                                      \
    acc[0] = make_float4(0.f,0.f,0.f,0.f); acc[1] = make_float4(0.f,0.f,0.f,0.f); \
    acc[2] = make_float4(0.f,0.f,0.f,0.f); acc[3] = make_float4(0.f,0.f,0.f,0.f); \
} while (0)

// ---------------- init ----------------
__global__ void init_kernel(const float* __restrict__ qp, const float* __restrict__ codes) {
    int i = blockIdx.x * blockDim.x + threadIdx.x;
    if (i < NPTS * HDIM)  { g_hq[i] = 0.0f; g_Q[i] = 0.0f; }  // Q0 = 0@W = 0
    if (i < NGRID * HDIM) g_hg[i] = codes[i];
    if (i < NPTS * 3)     g_xq[i] = qp[i];
}

// ---------- fused fp16 fragment packer for all 5 weight groups ----------
// fragment u32 index m (within a group's layer): j=m&3, lane=(m>>2)&31, slot=m>>7
//   s8=slot&7, k16=slot>>3; nt=s8*2+(j>>1); n=nt*8+(lane>>2)
//   k=k16*16+(lane&3)*2+(j&1)*8; value=half2(src[k][n], src[k+1][n])
__device__ __forceinline__ void pack_one(const float* S, uint32_t* dst, int m) {
    int j = m & 3;
    int lane = (m >> 2) & 31;
    int slot = m >> 7;
    int s8 = slot & 7;
    int k16 = slot >> 3;
    int nt = s8 * 2 + (j >> 1);
    int n = nt * 8 + (lane >> 2);
    int k = k16 * 16 + (lane & 3) * 2 + ((j & 1) << 3);
    dst[m] = f2h2(S[k * 128 + n], S[(k + 1) * 128 + n]);
}
// segments (u32 counts): W2H 32768 | W1H 65536 | WnH 32768 | WqH 32768 | WgH 32768
__global__ void pack_all_kernel(const float* __restrict__ eW2,
                                const float* __restrict__ nW1,
                                const float* __restrict__ nW2,
                                const float* __restrict__ eW1) {
    int i = blockIdx.x * blockDim.x + threadIdx.x;
    if (i < 32768) {
        int layer = i >> 13;
        pack_one(eW2 + (size_t)layer * 16384, g_W2H + layer * 8192, i & 8191);
    } else if (i < 98304) {
        int r = i - 32768;
        int layer = r >> 14;
        pack_one(nW1 + (size_t)layer * 32768, g_W1H + layer * 16384, r & 16383);
    } else if (i < 131072) {
        int r = i - 98304;
        int layer = r >> 13;
        pack_one(nW2 + (size_t)layer * 16384, g_WnH + layer * 8192, r & 8191);
    } else if (i < 163840) {
        int r = i - 131072;
        int layer = r >> 13;
        pack_one(eW1 + (size_t)layer * 257 * 128 + 128 * 128, g_WqH + layer * 8192, r & 8191);
    } else if (i < 196608) {
        int r = i - 163840;
        int layer = r >> 13;
        pack_one(eW1 + (size_t)layer * 257 * 128, g_WgH + layer * 8192, r & 8191);
    }
}

// ---------------- proj0: grid nodes only, layer 0 (scalar, fp32) ----------------
#define PK 20
__global__ __launch_bounds__(128) void proj_kernel(const float* __restrict__ eW1) {
    __shared__ float sAp[HDIM * PK];
    const int tid = threadIdx.x;
    const int j4 = (tid & 31) * 4;
    const int mq = tid >> 5;
    const int gbase = blockIdx.x * 16;
    const float* W = eW1;    // layer 0, rows 0:128 (grid half)

    #pragma unroll
    for (int n = 0; n < 16; ++n)
        sAp[tid * PK + n] = g_hg[(gbase + n) * HDIM + tid];
    __syncthreads();

    float4 acc[4]; ZERO4(acc);
    #pragma unroll 4
    for (int k = 0; k < HDIM; ++k) {
        float4 a = *(const float4*)(sAp + k * PK + mq * 4);
        float4 b = ldg4(W + k * HDIM + j4);
        FMA_TILE(acc, a, b);
    }
    #pragma unroll
    for (int mi = 0; mi < 4; ++mi)
        *(float4*)(g_P + (gbase + mq * 4 + mi) * HDIM + j4) = acc[mi];
}

// ---------------- edge kernel: fp16 mma, 64 edges (4 queries) per block ----------
// dyn smem: sA half [64][136] = 17408; sM float [64][132] = 33792; misc
#define OFF_M     17408
#define OFF_GIDX  51200
#define OFF_DIST  51456
#define OFF_DX    51712
#define OFF_DY    51968
#define OFF_DZ    52224
#define OFF_CM    52480
#define OFF_B2    52736
#define OFF_B1    53248
#define OFF_WD    53760
#define OFF_FC    54272
#define OFF_COEF  56832
#define OFF_Q     58112     // sQ [4][132] floats = 2112
#define EDGE_SMEM 60416

template <int TOUT>
__global__ __launch_bounds__(256) void edge_mma_kernel(
    const int*   __restrict__ erow,
    const float* __restrict__ gpts,
    const float* __restrict__ eW1, const float* __restrict__ eb1,
    const float* __restrict__ eb2,
    const float* __restrict__ coefW, const float* __restrict__ coefB,
    const float* __restrict__ qpts, float* __restrict__ out, int layer)
{
    extern __shared__ char sb[];
    __half* sA   = (__half*)sb;                  // [64][136]
    float* sM    = (float*)(sb + OFF_M);         // [64][132]
    int*   sGidx = (int*)  (sb + OFF_GIDX);
    float* sDist = (float*)(sb + OFF_DIST);
    float* sDx   = (float*)(sb + OFF_DX);
    float* sDy   = (float*)(sb + OFF_DY);
    float* sDz   = (float*)(sb + OFF_DZ);
    float* sCm   = (float*)(sb + OFF_CM);
    float* sB2   = (float*)(sb + OFF_B2);
    float* sB1   = (float*)(sb + OFF_B1);
    float* sWd   = (float*)(sb + OFF_WD);
    float* sFc   = (float*)(sb + OFF_FC);
    float* sCoef = (float*)(sb + OFF_COEF);
    float* sQ    = (float*)(sb + OFF_Q);

    const int tid = threadIdx.x;
    const int wid = tid >> 5;
    const int lane = tid & 31;
    const int bq4 = blockIdx.x * 4;
    const float* W1L = eW1 + (size_t)layer * 257 * HDIM;

    if (tid < 128) {
        sB2[tid] = eb2[layer * HDIM + tid];
        sB1[tid] = eb1[layer * HDIM + tid];
        sWd[tid] = W1L[256 * HDIM + tid];
        #pragma unroll
        for (int t = 0; t < TOUT; ++t) sFc[tid * TOUT + t] = coefW[tid * TOUT + t];
    } else {
        int t = tid - 128;                 // 128 threads: stage Q rows (4 x 128)
        int q = t >> 5;
        int k4 = (t & 31) * 4;
        *(float4*)(sQ + q * 132 + k4) = ldg4(g_Q + (bq4 + q) * HDIM + k4);
    }
    if (tid < 64) {
        int e = tid;
        int q = bq4 + (e >> 4);
        int rv = erow[q * DEG + (e & 15)];
        int gidx = rv - NPTS;
        int gl = gidx & (GPTS - 1);
        float rx = gpts[gl * 3 + 0] - g_xq[q * 3 + 0];
        float ry = gpts[gl * 3 + 1] - g_xq[q * 3 + 1];
        float rz = gpts[gl * 3 + 2] - g_xq[q * 3 + 2];
        float d = sqrtf(rx * rx + ry * ry + rz * rz);
        float inv = 1.0f / (d + 1e-8f);
        sGidx[e] = gidx; sDist[e] = d;
        sDx[e] = rx * inv; sDy[e] = ry * inv; sDz[e] = rz * inv;
        float cm = 0.5f * (__cosf(d * (float)(M_PI / 10.0)) + 1.0f);
        sCm[e] = (d <= 10.0f) ? cm : 0.0f;
    }
    __syncthreads();

    // stage 1: A[e][k] = f16(silu(Q[q][k] + P[gidx][k] + dist*wd[k] + b1[k]))
    #pragma unroll
    for (int it = 0; it < 8; ++it) {
        int idx = tid + it * 256;
        int e = idx >> 5;
        int k4 = (idx & 31) * 4;
        float4 Qv = *(const float4*)(sQ + (e >> 4) * 132 + k4);
        float4 Pv = ldg4(g_P + sGidx[e] * HDIM + k4);
        float4 wd = *(const float4*)(sWd + k4);
        float4 b1 = *(const float4*)(sB1 + k4);
        float dd = sDist[e];
        uint2 hv;
        hv.x = f2h2(silu_f(Qv.x + Pv.x + dd * wd.x + b1.x),
                    silu_f(Qv.y + Pv.y + dd * wd.y + b1.y));
        hv.y = f2h2(silu_f(Qv.z + Pv.z + dd * wd.z + b1.z),
                    silu_f(Qv.w + Pv.w + dd * wd.w + b1.w));
        *(uint2*)(sA + e * 136 + k4) = hv;
    }
    __syncthreads();

    // mma: warp grid 2(m) x 4(n); warp tile 32 rows x 32 cols; k16 steps
    const int mw = wid & 1;
    const int nw = wid >> 1;
    const int r4 = lane >> 2;
    const int kl = lane & 3;
    float c[2][4][4];
    #pragma unroll
    for (int s = 0; s < 2; ++s)
        #pragma unroll
        for (int ln = 0; ln < 4; ++ln)
            #pragma unroll
            for (int i = 0; i < 4; ++i) c[s][ln][i] = 0.0f;

    {
        const uint4* bfrag = (const uint4*)(g_W2H + layer * 8192);
        uint4 bq0 = __ldg(&bfrag[(nw * 2 + 0) * 32 + lane]);
        uint4 bq1 = __ldg(&bfrag[(nw * 2 + 1) * 32 + lane]);
        #pragma unroll
        for (int k16 = 0; k16 < 8; ++k16) {
            uint4 nb0, nb1;
            if (k16 < 7) {
                nb0 = __ldg(&bfrag[((k16 + 1) * 8 + nw * 2 + 0) * 32 + lane]);
                nb1 = __ldg(&bfrag[((k16 + 1) * 8 + nw * 2 + 1) * 32 + lane]);
            }
            int kb = k16 * 16 + kl * 2;
            uint32_t a[2][4];
            #pragma unroll
            for (int s = 0; s < 2; ++s) {
                int rb = mw * 32 + s * 16 + r4;
                a[s][0] = *(const uint32_t*)(sA + rb * 136 + kb);
                a[s][1] = *(const uint32_t*)(sA + (rb + 8) * 136 + kb);
                a[s][2] = *(const uint32_t*)(sA + rb * 136 + kb + 8);
                a[s][3] = *(const uint32_t*)(sA + (rb + 8) * 136 + kb + 8);
            }
            #pragma unroll
            for (int s = 0; s < 2; ++s) {
                mma_f16(c[s][0], a[s], bq0.x, bq0.y);
                mma_f16(c[s][1], a[s], bq0.z, bq0.w);
                mma_f16(c[s][2], a[s], bq1.x, bq1.y);
                mma_f16(c[s][3], a[s], bq1.z, bq1.w);
            }
            bq0 = nb0; bq1 = nb1;
        }
    }
    __syncthreads();

    // epilogue: M[e][j] = silu(D + b2[j]) * Cm[e], fp32 into sM
    #pragma unroll
    for (int s = 0; s < 2; ++s) {
        int r0 = mw * 32 + s * 16 + r4;
        int r1 = r0 + 8;
        float cm0 = sCm[r0], cm1 = sCm[r1];
        #pragma unroll
        for (int ln = 0; ln < 4; ++ln) {
            int c0 = nw * 32 + ln * 8 + 2 * kl;
            float bz0 = sB2[c0], bz1 = sB2[c0 + 1];
            *(float2*)(sM + r0 * 132 + c0) =
                make_float2(silu_f(c[s][ln][0] + bz0) * cm0, silu_f(c[s][ln][1] + bz1) * cm0);
            *(float2*)(sM + r1 * 132 + c0) =
                make_float2(silu_f(c[s][ln][2] + bz0) * cm1, silu_f(c[s][ln][3] + bz1) * cm1);
        }
    }
    __syncthreads();

    // m_aggr (layers 0..2)
    if (TOUT == 1) {
        #pragma unroll
        for (int it = 0; it < 2; ++it) {
            int idx = tid + it * 256;
            int q = idx >> 7;
            int j = idx & 127;
            float s = 0.0f;
            #pragma unroll
            for (int e = 0; e < DEG; ++e) s += sM[(q * DEG + e) * 132 + j];
            g_summ[(bq4 + q) * HDIM + j] = s * (1.0f / DEG);
        }
    }

    // coef: 64 edges, 4 threads/edge (interleaved cols -> conflict-free)
    {
        int e = tid >> 2, part = tid & 3;
        float acc[TOUT];
        #pragma unroll
        for (int t = 0; t < TOUT; ++t) acc[t] = 0.0f;
        const float* mr = sM + e * 132;
        #pragma unroll 8
        for (int i = 0; i < 32; ++i) {
            int j = i * 4 + part;
            float mv = mr[j];
            #pragma unroll
            for (int t = 0; t < TOUT; ++t) acc[t] = fmaf(mv, sFc[j * TOUT + t], acc[t]);
        }
        #pragma unroll
        for (int t = 0; t < TOUT; ++t) {
            float v = acc[t];
            v += __shfl_down_sync(0xFFFFFFFFu, v, 2);
            v += __shfl_down_sync(0xFFFFFFFFu, v, 1);
            if (part == 0) sCoef[e * TOUT + t] = v + __ldg(&coefB[t]);
        }
    }
    __syncthreads();

    // final reduction over 16 edges per query
    if (TOUT == 1) {
        if (tid < 12) {
            int q = tid / 3, d = tid % 3;
            const float* dirp = (d == 0) ? sDx : (d == 1) ? sDy : sDz;
            float s = 0.0f;
            #pragma unroll
            for (int e = 0; e < DEG; ++e) s += sCoef[q * DEG + e] * dirp[q * DEG + e];
            g_xq[(bq4 + q) * 3 + d] += s * (1.0f / DEG);
        }
    } else {
        if (tid < 4 * TOUT * 3) {
            int q = tid / (TOUT * 3);
            int r = tid % (TOUT * 3);
            int t = r / 3, d = r % 3;
            const float* dirp = (d == 0) ? sDx : (d == 1) ? sDy : sDz;
            float s = 0.0f;
            #pragma unroll
            for (int e = 0; e < DEG; ++e)
                s += sCoef[(q * DEG + e) * TOUT + t] * dirp[q * DEG + e];
            int gq = bq4 + q;
            out[(gq * TFIN + t) * 3 + d] =
                (g_xq[gq * 3 + d] - qpts[gq * 3 + d]) + s * (1.0f / DEG);
        }
    }
}

// -------- node kernel (fused): h-update + projection for next layer, fp16 mma ----
__global__ __launch_bounds__(256) void node_mma_kernel(
    const float* __restrict__ nb1_, const float* __restrict__ nb2_,
    int layer, int nextL)
{
    __shared__ __align__(16) __half sIn[64 * 264];  // A1 [64][264]; later [64][136]
    __shared__ float sB1[128], sB2[128];

    const int tid = threadIdx.x;
    const int wid = tid >> 5;
    const int lane = tid & 31;
    const int base = blockIdx.x * 64;
    const bool isq = (base < NPTS);
    const float* hsrc = isq ? (g_hq + base * HDIM) : (g_hg + (base - NPTS) * HDIM);
    float* hdst = isq ? (g_hq + base * HDIM) : (g_hg + (base - NPTS) * HDIM);

    if (tid < 128) {
        sB1[tid] = nb1_[layer * HDIM + tid];
        sB2[tid] = nb2_[layer * HDIM + tid];
    }

    // A-stage: In[row][0:128]=h, [128:256]=m_aggr (0 for grid), fp16
    #pragma unroll
    for (int it = 0; it < 16; ++it) {
        int idx = tid + it * 256;
        int row = idx >> 6;
        int c4 = (idx & 63) * 4;
        float4 v;
        if (c4 < 128) {
            v = ldg4(hsrc + row * HDIM + c4);
        } else if (isq) {
            v = ldg4(g_summ + (base + row) * HDIM + (c4 - 128));
        } else {
            v = make_float4(0.f, 0.f, 0.f, 0.f);
        }
        uint2 hv;
        hv.x = f2h2(v.x, v.y);
        hv.y = f2h2(v.z, v.w);
        *(uint2*)(sIn + row * 264 + c4) = hv;
    }
    __syncthreads();

    const int mw = wid & 1;
    const int nw = wid >> 1;
    const int r4 = lane >> 2;
    const int kl = lane & 3;

    float c[2][4][4];
    #pragma unroll
    for (int s = 0; s < 2; ++s)
        #pragma unroll
        for (int ln = 0; ln < 4; ++ln)
            #pragma unroll
            for (int i = 0; i < 4; ++i) c[s][ln][i] = 0.0f;

    // GEMM1: [64x256] @ W1 -> 64x128
    {
        const uint4* bfrag = (const uint4*)(g_W1H + layer * 16384);
        uint4 bq0 = __ldg(&bfrag[(nw * 2 + 0) * 32 + lane]);
        uint4 bq1 = __ldg(&bfrag[(nw * 2 + 1) * 32 + lane]);
        #pragma unroll
        for (int k16 = 0; k16 < 16; ++k16) {
            uint4 nb0, nb1;
            if (k16 < 15) {
                nb0 = __ldg(&bfrag[((k16 + 1) * 8 + nw * 2 + 0) * 32 + lane]);
                nb1 = __ldg(&bfrag[((k16 + 1) * 8 + nw * 2 + 1) * 32 + lane]);
            }
            int kb = k16 * 16 + kl * 2;
            uint32_t a[2][4];
            #pragma unroll
            for (int s = 0; s < 2; ++s) {
                int rb = mw * 32 + s * 16 + r4;
                a[s][0] = *(const uint32_t*)(sIn + rb * 264 + kb);
                a[s][1] = *(const uint32_t*)(sIn + (rb + 8) * 264 + kb);
                a[s][2] = *(const uint32_t*)(sIn + rb * 264 + kb + 8);
                a[s][3] = *(const uint32_t*)(sIn + (rb + 8) * 264 + kb + 8);
            }
            #pragma unroll
            for (int s = 0; s < 2; ++s) {
                mma_f16(c[s][0], a[s], bq0.x, bq0.y);
                mma_f16(c[s][1], a[s], bq0.z, bq0.w);
                mma_f16(c[s][2], a[s], bq1.x, bq1.y);
                mma_f16(c[s][3], a[s], bq1.z, bq1.w);
            }
            bq0 = nb0; bq1 = nb1;
        }
    }
    __syncthreads();   // all warps done reading sIn (A1)

    // U = f16(silu(acc + b1)), into sIn reused as [64][136]
    #pragma unroll
    for (int s = 0; s < 2; ++s) {
        int r0 = mw * 32 + s * 16 + r4;
        int r1 = r0 + 8;
        #pragma unroll
        for (int ln = 0; ln < 4; ++ln) {
            int c0 = nw * 32 + ln * 8 + 2 * kl;
            float bz0 = sB1[c0], bz1 = sB1[c0 + 1];
            *(uint32_t*)(sIn + r0 * 136 + c0) =
                f2h2(silu_f(c[s][ln][0] + bz0), silu_f(c[s][ln][1] + bz1));
            *(uint32_t*)(sIn + r1 * 136 + c0) =
                f2h2(silu_f(c[s][ln][2] + bz0), silu_f(c[s][ln][3] + bz1));
        }
    }
    __syncthreads();

    // GEMM2: U[64x128] @ W2 -> 64x128
    #pragma unroll
    for (int s = 0; s < 2; ++s)
        #pragma unroll
        for (int ln = 0; ln < 4; ++ln)
            #pragma unroll
            for (int i = 0; i < 4; ++i) c[s][ln][i] = 0.0f;
    {
        const uint4* bfrag = (const uint4*)(g_WnH + layer * 8192);
        uint4 bq0 = __ldg(&bfrag[(nw * 2 + 0) * 32 + lane]);
        uint4 bq1 = __ldg(&bfrag[(nw * 2 + 1) * 32 + lane]);
        #pragma unroll
        for (int k16 = 0; k16 < 8; ++k16) {
            uint4 nb0, nb1;
            if (k16 < 7) {
                nb0 = __ldg(&bfrag[((k16 + 1) * 8 + nw * 2 + 0) * 32 + lane]);
                nb1 = __ldg(&bfrag[((k16 + 1) * 8 + nw * 2 + 1) * 32 + lane]);
            }
            int kb = k16 * 16 + kl * 2;
            uint32_t a[2][4];
            #pragma unroll
            for (int s = 0; s < 2; ++s) {
                int rb = mw * 32 + s * 16 + r4;
                a[s][0] = *(const uint32_t*)(sIn + rb * 136 + kb);
                a[s][1] = *(const uint32_t*)(sIn + (rb + 8) * 136 + kb);
                a[s][2] = *(const uint32_t*)(sIn + rb * 136 + kb + 8);
                a[s][3] = *(const uint32_t*)(sIn + (rb + 8) * 136 + kb + 8);
            }
            #pragma unroll
            for (int s = 0; s < 2; ++s) {
                mma_f16(c[s][0], a[s], bq0.x, bq0.y);
                mma_f16(c[s][1], a[s], bq0.z, bq0.w);
                mma_f16(c[s][2], a[s], bq1.x, bq1.y);
                mma_f16(c[s][3], a[s], bq1.z, bq1.w);
            }
            bq0 = nb0; bq1 = nb1;
        }
    }
    __syncthreads();   // all warps done reading sIn (U) before overwrite

    // h_new = hold + D + b2: write global AND stage f16(h_new) into sIn [64][136]
    #pragma unroll
    for (int s = 0; s < 2; ++s) {
        int r0 = mw * 32 + s * 16 + r4;
        int r1 = r0 + 8;
        #pragma unroll
        for (int ln = 0; ln < 4; ++ln) {
            int c0 = nw * 32 + ln * 8 + 2 * kl;
            float bz0 = sB2[c0], bz1 = sB2[c0 + 1];
            float2 h0 = *(const float2*)(hdst + r0 * HDIM + c0);
            float2 h1 = *(const float2*)(hdst + r1 * HDIM + c0);
            float2 n0 = make_float2(h0.x + c[s][ln][0] + bz0, h0.y + c[s][ln][1] + bz1);
            float2 n1 = make_float2(h1.x + c[s][ln][2] + bz0, h1.y + c[s][ln][3] + bz1);
            *(float2*)(hdst + r0 * HDIM + c0) = n0;
            *(float2*)(hdst + r1 * HDIM + c0) = n1;
            *(uint32_t*)(sIn + r0 * 136 + c0) = f2h2(n0.x, n0.y);
            *(uint32_t*)(sIn + r1 * 136 + c0) = f2h2(n1.x, n1.y);
        }
    }
    __syncthreads();

    // GEMM3 (fused projection): P/Q[nextL] = h_new[64x128] @ We1half -> 64x128
    #pragma unroll
    for (int s = 0; s < 2; ++s)
        #pragma unroll
        for (int ln = 0; ln < 4; ++ln)
            #pragma unroll
            for (int i = 0; i < 4; ++i) c[s][ln][i] = 0.0f;
    {
        const uint32_t* wsrc = isq ? g_WqH : g_WgH;
        const uint4* bfrag = (const uint4*)(wsrc + nextL * 8192);
        uint4 bq0 = __ldg(&bfrag[(nw * 2 + 0) * 32 + lane]);
        uint4 bq1 = __ldg(&bfrag[(nw * 2 + 1) * 32 + lane]);
        #pragma unroll
        for (int k16 = 0; k16 < 8; ++k16) {
            uint4 nb0, nb1;
            if (k16 < 7) {
                nb0 = __ldg(&bfrag[((k16 + 1) * 8 + nw * 2 + 0) * 32 + lane]);
                nb1 = __ldg(&bfrag[((k16 + 1) * 8 + nw * 2 + 1) * 32 + lane]);
            }
            int kb = k16 * 16 + kl * 2;
            uint32_t a[2][4];
            #pragma unroll
            for (int s = 0; s < 2; ++s) {
                int rb = mw * 32 + s * 16 + r4;
                a[s][0] = *(const uint32_t*)(sIn + rb * 136 + kb);
                a[s][1] = *(const uint32_t*)(sIn + (rb + 8) * 136 + kb);
                a[s][2] = *(const uint32_t*)(sIn + rb * 136 + kb + 8);
                a[s][3] = *(const uint32_t*)(sIn + (rb + 8) * 136 + kb + 8);
            }
            #pragma unroll
            for (int s = 0; s < 2; ++s) {
                mma_f16(c[s][0], a[s], bq0.x, bq0.y);
                mma_f16(c[s][1], a[s], bq0.z, bq0.w);
                mma_f16(c[s][2], a[s], bq1.x, bq1.y);
                mma_f16(c[s][3], a[s], bq1.z, bq1.w);
            }
            bq0 = nb0; bq1 = nb1;
        }
    }

    // write projection (no bias)
    {
        float* outp = isq ? (g_Q + base * HDIM) : (g_P + (base - NPTS) * HDIM);
        #pragma unroll
        for (int s = 0; s < 2; ++s) {
            int r0 = mw * 32 + s * 16 + r4;
            int r1 = r0 + 8;
            #pragma unroll
            for (int ln = 0; ln < 4; ++ln) {
                int c0 = nw * 32 + ln * 8 + 2 * kl;
                *(float2*)(outp + r0 * HDIM + c0) = make_float2(c[s][ln][0], c[s][ln][1]);
                *(float2*)(outp + r1 * HDIM + c0) = make_float2(c[s][ln][2], c[s][ln][3]);
            }
        }
    }
}

// ---------------- launch ----------------
extern "C" void kernel_launch(void* const* d_in, const int* in_sizes, int n_in,
                              void* d_out, int out_size) {
    const float* qp    = (const float*)d_in[0];
    const float* codes = (const float*)d_in[1];
    const float* gpts  = (const float*)d_in[2];
    const float* eW1   = (const float*)d_in[3];
    const float* eb1   = (const float*)d_in[4];
    const float* eW2   = (const float*)d_in[5];
    const float* eb2   = (const float*)d_in[6];
    const float* cW    = (const float*)d_in[7];
    const float* cb    = (const float*)d_in[8];
    const float* fcW   = (const float*)d_in[9];
    const float* fcb   = (const float*)d_in[10];
    const float* nW1   = (const float*)d_in[11];
    const float* nb1   = (const float*)d_in[12];
    const float* nW2   = (const float*)d_in[13];
    const float* nb2   = (const float*)d_in[14];
    const int*   eidx  = (const int*)d_in[15];
    float* out = (float*)d_out;

    static bool attr_done = false;
    if (!attr_done) {
        cudaFuncSetAttribute(edge_mma_kernel<1>,
                             cudaFuncAttributeMaxDynamicSharedMemorySize, EDGE_SMEM);
        cudaFuncSetAttribute(edge_mma_kernel<TFIN>,
                             cudaFuncAttributeMaxDynamicSharedMemorySize, EDGE_SMEM);
        attr_done = true;
    }

    init_kernel<<<(NPTS * HDIM + 255) / 256, 256>>>(qp, codes);
    pack_all_kernel<<<(196608 + 255) / 256, 256>>>(eW2, nW1, nW2, eW1);

    // layer-0 projection: queries are zero (handled in init); grid = codes @ We1[0]
    proj_kernel<<<NGRID / 16, 128>>>(eW1);

    for (int L = 0; L < 4; ++L) {
        if (L < 3) {
            edge_mma_kernel<1><<<NPTS / 4, 256, EDGE_SMEM>>>(
                eidx, gpts, eW1, eb1, eb2, cW + L * HDIM, cb + L, qp, nullptr, L);
            node_mma_kernel<<<NNODES / 64, 256>>>(nb1, nb2, L, L + 1);
        } else {
            edge_mma_kernel<TFIN><<<NPTS / 4, 256, EDGE_SMEM>>>(
                eidx, gpts, eW1, eb1, eb2, fcW, fcb, qp, out, L);
        }
    }
}